// round 15
// baseline (speedup 1.0000x reference)
#include <cuda_runtime.h>
#include <math.h>

typedef unsigned long long u64;

// ---------------- packed f32x2 helpers (Blackwell FFMA2 path) ----------------
__device__ __forceinline__ void ffma2(u64 &d, u64 a, u64 b) {
    asm("fma.rn.f32x2 %0, %1, %2, %0;" : "+l"(d) : "l"(a), "l"(b));
}
__device__ __forceinline__ u64 fadd2(u64 a, u64 b) {
    u64 r; asm("add.rn.f32x2 %0, %1, %2;" : "=l"(r) : "l"(a), "l"(b)); return r;
}
__device__ __forceinline__ u64 dup2(float x) {
    u64 r; asm("mov.b64 %0, {%1, %1};" : "=l"(r) : "f"(x)); return r;
}
__device__ __forceinline__ u64 pack2(float lo, float hi) {
    u64 r; asm("mov.b64 %0, {%1, %2};" : "=l"(r) : "f"(lo), "f"(hi)); return r;
}
__device__ __forceinline__ float2 unpk(u64 v) {
    float2 f; asm("mov.b64 {%0, %1}, %2;" : "=f"(f.x), "=f"(f.y) : "l"(v)); return f;
}

// ---------------- tf32 mma helpers ----------------
__device__ __forceinline__ unsigned f2tf(float v) {
    unsigned r; asm("cvt.rna.tf32.f32 %0, %1;" : "=r"(r) : "f"(v)); return r;
}
__device__ __forceinline__ void mma_tf32(
    float &d0, float &d1, float &d2, float &d3,
    unsigned a0, unsigned a1, unsigned a2, unsigned a3,
    unsigned b0, unsigned b1)
{
    asm("mma.sync.aligned.m16n8k8.row.col.f32.tf32.tf32.f32 "
        "{%0,%1,%2,%3}, {%4,%5,%6,%7}, {%8,%9}, {%0,%1,%2,%3};"
        : "+f"(d0), "+f"(d1), "+f"(d2), "+f"(d3)
        : "r"(a0), "r"(a1), "r"(a2), "r"(a3), "r"(b0), "r"(b1));
}

// ---------------- scratch (no allocation allowed) ----------------
__device__ float  g_bufA[32u*64*128*128];
__device__ float  g_bufB[32u*64*128*128];
__device__ float  g_bufC[32u*64*32*32];
__device__ u64    g_best[32768];
__device__ float  g_counts[2048];
__device__ float  g_cnorm[2048];
__device__ double g_vq_ss;
__device__ double g_recon_ss;

// ---------------- helpers ----------------
__device__ __forceinline__ float block_sum(float v) {
    __shared__ float sh[256];
    int t = threadIdx.x;
    sh[t] = v; __syncthreads();
    #pragma unroll
    for (int s = 128; s > 0; s >>= 1) {
        if (t < s) sh[t] += sh[t + s];
        __syncthreads();
    }
    return sh[0];
}

__global__ void init_k() {
    int i = blockIdx.x * 256 + threadIdx.x;
    if (i < 32768) g_best[i] = 0xFFFFFFFFFFFFFFFFull;
    if (i < 2048) g_counts[i] = 0.f;
    if (i == 0) { g_vq_ss = 0.0; g_recon_ss = 0.0; }
}

// =====================================================================
// conv k4 s2 p1 -> 64 co, tf32 tensor cores, BN(+ReLU) fused.
// GEMM: A = W [64co x K], B = parity-split im2col [K x 128 sp].
// Warp = 16 co x 64 sp; K-loop = 8-ci chunks x 16 taps. Dynamic SMEM.
// =====================================================================
template<int CIN, int OW, bool RELU>
__global__ __launch_bounds__(256) void conv4s2_mma(
    const float* __restrict__ in, float* __restrict__ out,
    const float* __restrict__ w, const float* __restrict__ bias,
    const float* __restrict__ bnp)
{
    constexpr int R = 128 / OW;
    constexpr int NR = 2 * R + 2;
    constexpr int P = OW + 1;
    constexpr int HIN = OW * 2;
    constexpr int RAW = NR * 2 * P;
    constexpr int CIST = (RAW % 32 <= 8) ? (RAW - RAW % 32 + 8)
                                         : (RAW - RAW % 32 + 40);
    constexpr int WSZ = 16 * 8 * 72;
    extern __shared__ unsigned dsm[];
    unsigned* sW  = dsm;            // [tap16][ci8][co pitch72]
    unsigned* sIn = dsm + WSZ;      // [ci8][CIST] parity-split rows
    const int t = threadIdx.x, lane = t & 31, wid = t >> 5;
    const int mw = wid & 3, nw = wid >> 2;
    const int grp = lane >> 2, tig = lane & 3;
    const int n = blockIdx.y, r0 = blockIdx.x * R;
    const int coW = mw * 16;
    const float* inb = in + (size_t)n * CIN * HIN * HIN;
    float acc[8][4];
    #pragma unroll
    for (int nt = 0; nt < 8; ++nt)
        #pragma unroll
        for (int i = 0; i < 4; ++i) acc[nt][i] = 0.f;

    for (int ci0 = 0; ci0 < CIN; ci0 += 8) {
        __syncthreads();
        for (int i = t; i < 8 * RAW; i += 256) {
            int ci = i / RAW, r2 = i - ci * RAW;
            int rr = r2 / (2 * P), r3 = r2 - rr * 2 * P;
            int p = r3 / P, cc = r3 - p * P;
            int gr = 2 * r0 - 1 + rr, gc = 2 * cc - p;
            int gci = ci0 + ci;
            float v = 0.f;
            if (gci < CIN && (unsigned)gr < (unsigned)HIN && (unsigned)gc < (unsigned)HIN)
                v = inb[(size_t)gci * (HIN * HIN) + gr * HIN + gc];
            sIn[ci * CIST + r2] = f2tf(v);
        }
        for (int i = t; i < 16 * 8 * 64; i += 256) {
            int tap = i >> 9, r2 = i & 511, ci = r2 >> 6, co = r2 & 63;
            int gci = ci0 + ci;
            float v = (gci < CIN) ? w[(co * CIN + gci) * 16 + tap] : 0.f;
            sW[(tap * 8 + ci) * 72 + co] = f2tf(v);
        }
        __syncthreads();
        #pragma unroll
        for (int kh = 0; kh < 4; ++kh) {
            #pragma unroll
            for (int kw = 0; kw < 4; ++kw) {
                const unsigned* wrow = sW + ((kh * 4 + kw) * 8) * 72 + coW + grp;
                unsigned a0 = wrow[tig * 72];
                unsigned a1 = wrow[tig * 72 + 8];
                unsigned a2 = wrow[(tig + 4) * 72];
                unsigned a3 = wrow[(tig + 4) * 72 + 8];
                const int pp = ((kw & 1) ^ 1) * P + (kw >> 1);
                #pragma unroll
                for (int nt = 0; nt < 8; ++nt) {
                    int sidx = nw * 64 + nt * 8;
                    int rowoff = sidx / OW, colb = sidx - rowoff * OW;
                    int idx = (2 * rowoff + kh) * (2 * P) + pp + colb + grp;
                    unsigned b0 = sIn[tig * CIST + idx];
                    unsigned b1 = sIn[(tig + 4) * CIST + idx];
                    mma_tf32(acc[nt][0], acc[nt][1], acc[nt][2], acc[nt][3],
                             a0, a1, a2, a3, b0, b1);
                }
            }
        }
    }
    const int co1 = coW + grp, co2 = co1 + 8;
    float sc1 = bnp[co1] * rsqrtf(bnp[192 + co1] + 1e-5f);
    float sc2 = bnp[co2] * rsqrtf(bnp[192 + co2] + 1e-5f);
    float sh1 = (bias[co1] - bnp[128 + co1]) * sc1 + bnp[64 + co1];
    float sh2 = (bias[co2] - bnp[128 + co2]) * sc2 + bnp[64 + co2];
    float* ob = out + (size_t)n * 64 * (OW * OW);
    #pragma unroll
    for (int nt = 0; nt < 8; ++nt) {
        int sidx = nw * 64 + nt * 8;
        int rowoff = sidx / OW, colb = sidx - rowoff * OW;
        int sp = (r0 + rowoff) * OW + colb + 2 * tig;
        float2 o1, o2;
        o1.x = acc[nt][0] * sc1 + sh1; o1.y = acc[nt][1] * sc1 + sh1;
        o2.x = acc[nt][2] * sc2 + sh2; o2.y = acc[nt][3] * sc2 + sh2;
        if (RELU) {
            o1.x = fmaxf(o1.x, 0.f); o1.y = fmaxf(o1.y, 0.f);
            o2.x = fmaxf(o2.x, 0.f); o2.y = fmaxf(o2.y, 0.f);
        }
        *(float2*)&ob[(size_t)co1 * (OW * OW) + sp] = o1;
        *(float2*)&ob[(size_t)co2 * (OW * OW) + sp] = o2;
    }
}

// =====================================================================
// conv 3x3 s1 p1, 64->64, H=W=32, tf32 tensor cores. (proven R14)
// =====================================================================
template<bool PRERELU, bool HAS_BN>
__global__ __launch_bounds__(256) void conv3x3_mma(
    const float* __restrict__ in, float* __restrict__ out,
    const float* __restrict__ w, const float* __restrict__ bias,
    const float* __restrict__ bnp)
{
    __shared__ unsigned sIn[8 * 6 * 36];
    __shared__ unsigned sW [9 * 8 * 72];
    const int t = threadIdx.x, lane = t & 31, wid = t >> 5;
    const int mw = wid & 3, nw = wid >> 2;
    const int grp = lane >> 2, tig = lane & 3;
    const int n = blockIdx.y, r0 = blockIdx.x << 2;
    const int coW = mw * 16;
    const float* inb = in + (size_t)n * 64 * 1024;
    float acc[8][4];
    #pragma unroll
    for (int nt = 0; nt < 8; ++nt)
        #pragma unroll
        for (int i = 0; i < 4; ++i) acc[nt][i] = 0.f;

    for (int ci0 = 0; ci0 < 64; ci0 += 8) {
        __syncthreads();
        for (int i = t; i < 8 * 6 * 34; i += 256) {
            int ci = i / 204, r2 = i - ci * 204, rr = r2 / 34, cc = r2 - rr * 34;
            int gr = r0 - 1 + rr, gc = cc - 1;
            float v = 0.f;
            if ((unsigned)gr < 32u && (unsigned)gc < 32u) {
                v = inb[(ci0 + ci) * 1024 + gr * 32 + gc];
                if (PRERELU) v = fmaxf(v, 0.f);
            }
            sIn[ci * 216 + rr * 36 + cc] = f2tf(v);
        }
        for (int i = t; i < 9 * 8 * 64; i += 256) {
            int tap = i >> 9, r2 = i & 511, ci = r2 >> 6, co = r2 & 63;
            sW[(tap * 8 + ci) * 72 + co] =
                f2tf(w[co * 576 + (ci0 + ci) * 9 + tap]);
        }
        __syncthreads();
        #pragma unroll
        for (int kh = 0; kh < 3; ++kh) {
            #pragma unroll
            for (int kw = 0; kw < 3; ++kw) {
                const unsigned* wrow = sW + ((kh * 3 + kw) * 8) * 72 + coW + grp;
                unsigned a0 = wrow[tig * 72];
                unsigned a1 = wrow[tig * 72 + 8];
                unsigned a2 = wrow[(tig + 4) * 72];
                unsigned a3 = wrow[(tig + 4) * 72 + 8];
                #pragma unroll
                for (int nt = 0; nt < 8; ++nt) {
                    int rr = 2 * nw + (nt >> 2) + kh;
                    int cc = (nt & 3) * 8 + grp + kw;
                    unsigned b0 = sIn[tig * 216 + rr * 36 + cc];
                    unsigned b1 = sIn[(tig + 4) * 216 + rr * 36 + cc];
                    mma_tf32(acc[nt][0], acc[nt][1], acc[nt][2], acc[nt][3],
                             a0, a1, a2, a3, b0, b1);
                }
            }
        }
    }
    const int co1 = coW + grp, co2 = co1 + 8;
    float sc1 = 1.f, sc2 = 1.f, sh1 = bias[co1], sh2 = bias[co2];
    if (HAS_BN) {
        sc1 = bnp[co1] * rsqrtf(bnp[192 + co1] + 1e-5f);
        sc2 = bnp[co2] * rsqrtf(bnp[192 + co2] + 1e-5f);
        sh1 = (sh1 - bnp[128 + co1]) * sc1 + bnp[64 + co1];
        sh2 = (sh2 - bnp[128 + co2]) * sc2 + bnp[64 + co2];
    }
    float* ob = out + (size_t)n * 64 * 1024;
    #pragma unroll
    for (int nt = 0; nt < 8; ++nt) {
        int sp = (r0 + 2 * nw + (nt >> 2)) * 32 + (nt & 3) * 8 + 2 * tig;
        float2 o1; o1.x = acc[nt][0] * sc1 + sh1; o1.y = acc[nt][1] * sc1 + sh1;
        float2 o2; o2.x = acc[nt][2] * sc2 + sh2; o2.y = acc[nt][3] * sc2 + sh2;
        *(float2*)&ob[co1 * 1024 + sp] = o1;
        *(float2*)&ob[co2 * 1024 + sp] = o2;
    }
}

// =====================================================================
// conv 1x1, 64->64, HW=1024, tf32 tensor cores. (proven R14)
// =====================================================================
template<bool PRERELU, bool HAS_BN, bool RES>
__global__ __launch_bounds__(256) void conv1x1_mma(
    const float* __restrict__ in, const float* __restrict__ res,
    float* __restrict__ out,
    const float* __restrict__ w, const float* __restrict__ bias,
    const float* __restrict__ bnp)
{
    __shared__ unsigned sIn[8 * 136];
    __shared__ unsigned sW [64 * 72];
    const int t = threadIdx.x, lane = t & 31, wid = t >> 5;
    const int mw = wid & 3, nw = wid >> 2;
    const int grp = lane >> 2, tig = lane & 3;
    const int n = blockIdx.y, sp0 = blockIdx.x * 128;
    const int coW = mw * 16;
    for (int i = t; i < 4096; i += 256) {
        int ci = i >> 6, co = i & 63;
        sW[ci * 72 + co] = f2tf(w[co * 64 + ci]);
    }
    float acc[8][4];
    #pragma unroll
    for (int nt = 0; nt < 8; ++nt)
        #pragma unroll
        for (int i = 0; i < 4; ++i) acc[nt][i] = 0.f;
    const float* inb = in + (size_t)n * 64 * 1024 + sp0;
    for (int ci0 = 0; ci0 < 64; ci0 += 8) {
        __syncthreads();
        for (int i = t; i < 1024; i += 256) {
            int ci = i >> 7, s = i & 127;
            float v = inb[(ci0 + ci) * 1024 + s];
            if (PRERELU) v = fmaxf(v, 0.f);
            sIn[ci * 136 + s] = f2tf(v);
        }
        __syncthreads();
        const unsigned* wrow = sW + ci0 * 72 + coW + grp;
        unsigned a0 = wrow[tig * 72];
        unsigned a1 = wrow[tig * 72 + 8];
        unsigned a2 = wrow[(tig + 4) * 72];
        unsigned a3 = wrow[(tig + 4) * 72 + 8];
        #pragma unroll
        for (int nt = 0; nt < 8; ++nt) {
            int cc = nw * 64 + nt * 8 + grp;
            unsigned b0 = sIn[tig * 136 + cc];
            unsigned b1 = sIn[(tig + 4) * 136 + cc];
            mma_tf32(acc[nt][0], acc[nt][1], acc[nt][2], acc[nt][3],
                     a0, a1, a2, a3, b0, b1);
        }
    }
    const int co1 = coW + grp, co2 = co1 + 8;
    float sc1 = 1.f, sc2 = 1.f, sh1 = bias[co1], sh2 = bias[co2];
    if (HAS_BN) {
        sc1 = bnp[co1] * rsqrtf(bnp[192 + co1] + 1e-5f);
        sc2 = bnp[co2] * rsqrtf(bnp[192 + co2] + 1e-5f);
        sh1 = (sh1 - bnp[128 + co1]) * sc1 + bnp[64 + co1];
        sh2 = (sh2 - bnp[128 + co2]) * sc2 + bnp[64 + co2];
    }
    float* ob = out + (size_t)n * 64 * 1024 + sp0;
    const float* rb = RES ? res + (size_t)n * 64 * 1024 + sp0 : nullptr;
    #pragma unroll
    for (int nt = 0; nt < 8; ++nt) {
        int sp = nw * 64 + nt * 8 + 2 * tig;
        float2 o1; o1.x = acc[nt][0] * sc1 + sh1; o1.y = acc[nt][1] * sc1 + sh1;
        float2 o2; o2.x = acc[nt][2] * sc2 + sh2; o2.y = acc[nt][3] * sc2 + sh2;
        if (RES) {
            float2 r1 = *(const float2*)&rb[co1 * 1024 + sp];
            float2 r2 = *(const float2*)&rb[co2 * 1024 + sp];
            o1.x += r1.x; o1.y += r1.y; o2.x += r2.x; o2.y += r2.y;
        }
        *(float2*)&ob[co1 * 1024 + sp] = o1;
        *(float2*)&ob[co2 * 1024 + sp] = o2;
    }
}

// =====================================================================
// conv-transpose k4 s2 p1, CIN=64. Branch-free 4-tap inner loop. (fp32x2)
// =====================================================================
template<int COUT, int OUTW, int R, bool PRERELU, bool TANH_LOSS>
__global__ __launch_bounds__(256) void convt_t(
    const float* __restrict__ in, float* __restrict__ out,
    const float* __restrict__ w, const float* __restrict__ bias,
    const float* __restrict__ xref)
{
    constexpr int HIN = OUTW / 2;
    constexpr int NRW = R + 1;
    constexpr int NC  = OUTW / 2 + 2;
    constexpr int NCP = (NC & 1) ? NC : NC + 1;
    constexpr int SPT = R * OUTW;
    constexpr int TXN = SPT / 4;
    constexpr int COS = (COUT == 64) ? 64 : 16;
    __shared__ __align__(16) float sIn[8 * NRW * NCP];
    __shared__ __align__(16) float sW [8 * 16 * 68];
    const int t = threadIdx.x, ty = t / TXN, tx = t % TXN;
    const int row = tx / (OUTW / 4), col4 = (tx % (OUTW / 4)) * 4;
    const int n = blockIdx.y, r0 = blockIdx.x * R;
    const int base_hi = ((r0 + 1) >> 1) - 1;
    const float* inb = in + (size_t)n * 64 * HIN * HIN;
    const int ho = r0 + row;
    const int kh_a = (ho + 1) & 1;
    const int rr_a = ((ho + 1) >> 1) - base_hi;
    int cc0[4], kwp[4];
    #pragma unroll
    for (int j = 0; j < 4; ++j) {
        int wo = col4 + j;
        kwp[j] = (wo + 1) & 1;
        cc0[j] = ((wo + 1) >> 1) + 1;
    }
    u64 acc[4][4];
    #pragma unroll
    for (int j = 0; j < 4; ++j)
        #pragma unroll
        for (int p = 0; p < 4; ++p) acc[j][p] = 0ull;

    for (int ci0 = 0; ci0 < 64; ci0 += 8) {
        __syncthreads();
        for (int i = t; i < 8 * NRW * NCP; i += 256) {
            int ci = i / (NRW * NCP), r2 = i - ci * (NRW * NCP);
            int rr = r2 / NCP, cc = r2 - rr * NCP;
            int gr = base_hi + rr, gc = cc - 1;
            float v = 0.f;
            if ((unsigned)gr < (unsigned)HIN && (unsigned)gc < (unsigned)HIN) {
                v = inb[(ci0 + ci) * (HIN * HIN) + gr * HIN + gc];
                if (PRERELU) v = fmaxf(v, 0.f);
            }
            sIn[i] = v;
        }
        for (int i = t; i < 8 * 16 * COS; i += 256) {
            int ci = i / (16 * COS), r2 = i - ci * (16 * COS);
            int co = r2 >> 4, tap = r2 & 15;
            float v = (co < COUT) ? w[((ci0 + ci) * COUT + co) * 16 + tap] : 0.f;
            sW[ci * 1088 + tap * 68 + co] = v;
        }
        __syncthreads();
        #pragma unroll
        for (int ci = 0; ci < 8; ++ci) {
            const float* rA = sIn + ci * (NRW * NCP) + rr_a * NCP;
            const float* rB = rA - NCP;
            const float* sWb = sW + ci * 1088 + ty * 8;
            #pragma unroll
            for (int jp = 0; jp < 2; ++jp) {
                int t0 = kh_a * 4 + kwp[jp];
                u64 wv[4][4];
                #pragma unroll
                for (int k = 0; k < 4; ++k) {
                    int tap = t0 + (k & 1) * 2 + (k >> 1) * 8;
                    const ulonglong2* wp = (const ulonglong2*)(sWb + tap * 68);
                    ulonglong2 wa = wp[0], wb = wp[1];
                    wv[k][0] = wa.x; wv[k][1] = wa.y; wv[k][2] = wb.x; wv[k][3] = wb.y;
                }
                #pragma unroll
                for (int jj = 0; jj < 2; ++jj) {
                    int j = jp + jj * 2;
                    int ca = cc0[j], cb = ca - 1;
                    u64 da = dup2(rA[ca]), db = dup2(rA[cb]);
                    u64 dc = dup2(rB[ca]), dd = dup2(rB[cb]);
                    #pragma unroll
                    for (int p = 0; p < 4; ++p) {
                        ffma2(acc[j][p], da, wv[0][p]);
                        ffma2(acc[j][p], db, wv[1][p]);
                        ffma2(acc[j][p], dc, wv[2][p]);
                        ffma2(acc[j][p], dd, wv[3][p]);
                    }
                }
            }
        }
    }
    float ls = 0.f;
    #pragma unroll
    for (int p = 0; p < 4; ++p) {
        float rr2[2][4];
        #pragma unroll
        for (int j = 0; j < 4; ++j) {
            float2 ff = unpk(acc[j][p]);
            rr2[0][j] = ff.x; rr2[1][j] = ff.y;
        }
        #pragma unroll
        for (int l = 0; l < 2; ++l) {
            int co = ty * 8 + 2 * p + l;
            if (co < COUT) {
                float b = bias[co];
                size_t oi = ((size_t)n * COUT + co) * ((size_t)OUTW * OUTW) + ho * OUTW + col4;
                float r[4];
                #pragma unroll
                for (int j = 0; j < 4; ++j) {
                    r[j] = rr2[l][j] + b;
                    if (TANH_LOSS) {
                        r[j] = tanhf(r[j]);
                        float d = r[j] - xref[oi + j];
                        ls += d * d;
                    } else {
                        r[j] = fmaxf(r[j], 0.f);
                    }
                }
                float4 o; o.x = r[0]; o.y = r[1]; o.z = r[2]; o.w = r[3];
                *(float4*)&out[oi] = o;
            }
        }
    }
    if (TANH_LOSS) {
        float s = block_sum(ls);
        if (t == 0) atomicAdd(&g_recon_ss, (double)s);
    }
}

// ---------------- VQ ----------------
__global__ void cnorm_k(const float* __restrict__ cb) {
    int k = blockIdx.x * 256 + threadIdx.x;
    if (k < 2048) {
        float s = 0.f;
        #pragma unroll
        for (int d = 0; d < 64; ++d) { float c = cb[k * 64 + d]; s += c * c; }
        g_cnorm[k] = s;
    }
}

__global__ __launch_bounds__(128) void vq_assign_k(
    const float* __restrict__ z, const float* __restrict__ cb)
{
    __shared__ __align__(16) float4 sc[128 * 16];
    __shared__ float  sn[128];
    const int row = blockIdx.x * 128 + threadIdx.x;
    const int q0 = blockIdx.y * 512;
    const int b = row >> 10, hw = row & 1023;
    u64 zr2[32];
    const float* zp = z + ((size_t)b * 64) * 1024 + hw;
    #pragma unroll
    for (int d2 = 0; d2 < 32; ++d2)
        zr2[d2] = pack2(zp[(2 * d2) * 1024], zp[(2 * d2 + 1) * 1024]);
    float best = 3.4e38f; int bi = 0;
    const float4* cb4 = (const float4*)cb;
    for (int k0 = q0; k0 < q0 + 512; k0 += 128) {
        __syncthreads();
        for (int i = threadIdx.x; i < 128 * 16; i += 128) sc[i] = cb4[k0 * 16 + i];
        sn[threadIdx.x] = g_cnorm[k0 + threadIdx.x];
        __syncthreads();
        for (int kk = 0; kk < 128; ++kk) {
            const ulonglong2* cp = (const ulonglong2*)(sc + kk * 16);
            u64 a0 = 0ull, a1 = 0ull, a2 = 0ull, a3 = 0ull;
            #pragma unroll
            for (int j = 0; j < 8; ++j) {
                ulonglong2 c0 = cp[2 * j], c1 = cp[2 * j + 1];
                ffma2(a0, zr2[4 * j + 0], c0.x);
                ffma2(a1, zr2[4 * j + 1], c0.y);
                ffma2(a2, zr2[4 * j + 2], c1.x);
                ffma2(a3, zr2[4 * j + 3], c1.y);
            }
            u64 s2 = fadd2(fadd2(a0, a1), fadd2(a2, a3));
            float2 f = unpk(s2);
            float dist = sn[kk] - 2.f * (f.x + f.y);
            if (dist < best) { best = dist; bi = k0 + kk; }
        }
    }
    unsigned int fb = __float_as_uint(best);
    unsigned int key = fb ^ (((int)fb >> 31) | 0x80000000u);
    u64 packed = ((u64)key << 32) | (unsigned)bi;
    atomicMin(&g_best[row], packed);
}

__global__ __launch_bounds__(256) void vq_gather_k(
    const float* __restrict__ z, const float* __restrict__ cb,
    float* __restrict__ quant)
{
    int gid = blockIdx.x * 256 + threadIdx.x;
    int b = gid >> 16;
    int rem = gid & 65535;
    int d = rem >> 10;
    int hw = rem & 1023;
    int k = (int)(unsigned)(g_best[(b << 10) + hw] & 0xFFFFFFFFull);
    float q = cb[k * 64 + d];
    float zv = z[gid];
    quant[gid] = q;
    float diff = q - zv;
    float s = block_sum(diff * diff);
    if (threadIdx.x == 0) atomicAdd(&g_vq_ss, (double)s);
}

__global__ void vq_counts_k() {
    int i = blockIdx.x * 256 + threadIdx.x;
    if (i < 32768) {
        int k = (int)(unsigned)(g_best[i] & 0xFFFFFFFFull);
        atomicAdd(&g_counts[k], 1.0f);
    }
}

// ---------------- finalize ----------------
__global__ void finalize_k(float* __restrict__ out2) {
    float s = 0.f;
    for (int k = threadIdx.x; k < 2048; k += 256) {
        float p = g_counts[k] * (1.0f / 32768.0f);
        s += p * logf(p + 1e-10f);
    }
    float tot = block_sum(s);
    if (threadIdx.x == 0) {
        float perp = expf(-tot);
        float loss = (float)(g_recon_ss / 31457280.0 + 1.25 * (g_vq_ss / 2097152.0));
        out2[0] = loss;
        out2[1] = perp;
    }
}

// ---------------- launcher ----------------
extern "C" void kernel_launch(void* const* d_in, const int* in_sizes, int n_in,
                              void* d_out, int out_size) {
    const float* x          = (const float*)d_in[0];
    const float* ew1        = (const float*)d_in[1];
    const float* eb1        = (const float*)d_in[2];
    const float* ew2        = (const float*)d_in[3];
    const float* eb2        = (const float*)d_in[4];
    const float* ew3        = (const float*)d_in[5];
    const float* eb3        = (const float*)d_in[6];
    const float* enc_bn     = (const float*)d_in[7];
    const float* enc_res_w3 = (const float*)d_in[8];
    const float* enc_res_b3 = (const float*)d_in[9];
    const float* enc_res_w1 = (const float*)d_in[10];
    const float* enc_res_b1 = (const float*)d_in[11];
    const float* enc_res_bn = (const float*)d_in[12];
    const float* enc_out_w  = (const float*)d_in[13];
    const float* enc_out_b  = (const float*)d_in[14];
    const float* codebook   = (const float*)d_in[15];
    const float* dec_in_w   = (const float*)d_in[16];
    const float* dec_in_b   = (const float*)d_in[17];
    const float* dec_res_w3 = (const float*)d_in[18];
    const float* dec_res_b3 = (const float*)d_in[19];
    const float* dec_res_w1 = (const float*)d_in[20];
    const float* dec_res_b1 = (const float*)d_in[21];
    const float* dec_res_bn = (const float*)d_in[22];
    const float* dt_w1      = (const float*)d_in[23];
    const float* dt_b1      = (const float*)d_in[24];
    const float* dt_w2      = (const float*)d_in[25];
    const float* dt_b2      = (const float*)d_in[26];
    const float* dt_w3      = (const float*)d_in[27];
    const float* dt_b3      = (const float*)d_in[28];

    void *pa, *pb, *pc;
    cudaGetSymbolAddress(&pa, g_bufA);
    cudaGetSymbolAddress(&pb, g_bufB);
    cudaGetSymbolAddress(&pc, g_bufC);
    float* A  = (float*)pa;
    float* Bb = (float*)pb;
    float* Cc = (float*)pc;
    float* out = (float*)d_out;

    // dynamic SMEM sizes: 16*8*72 weights + 8*CIST input (u32 words)
    const int smem1 = (16 * 8 * 72 + 8 * 1032) * 4;   // OW=128 -> 69888 B
    const int smem2 = (16 * 8 * 72 + 8 * 808)  * 4;   // OW=64  -> 62720 B
    const int smem3 = (16 * 8 * 72 + 8 * 680)  * 4;   // OW=32  -> 58624 B
    cudaFuncSetAttribute(conv4s2_mma<15, 128, true >,
                         cudaFuncAttributeMaxDynamicSharedMemorySize, smem1);
    cudaFuncSetAttribute(conv4s2_mma<64, 64, true >,
                         cudaFuncAttributeMaxDynamicSharedMemorySize, smem2);
    cudaFuncSetAttribute(conv4s2_mma<64, 32, false>,
                         cudaFuncAttributeMaxDynamicSharedMemorySize, smem3);

    init_k<<<128, 256>>>();

    // ---- Encoder ----
    conv4s2_mma<15, 128, true ><<<dim3(128, 32), 256, smem1>>>(x,  A,  ew1, eb1, enc_bn);
    conv4s2_mma<64, 64,  true ><<<dim3(32, 32),  256, smem2>>>(A,  Bb, ew2, eb2, enc_bn + 256);
    conv4s2_mma<64, 32,  false><<<dim3(8, 32),   256, smem3>>>(Bb, A,  ew3, eb3, enc_bn + 512);
    for (int i = 0; i < 4; ++i) {
        conv3x3_mma<true, true><<<dim3(8, 32), 256>>>(
            A, Bb, enc_res_w3 + (size_t)i * 36864, enc_res_b3 + i * 64,
            enc_res_bn + i * 512);
        conv1x1_mma<true, true, true><<<dim3(8, 32), 256>>>(
            Bb, A, A, enc_res_w1 + (size_t)i * 4096, enc_res_b1 + i * 64,
            enc_res_bn + i * 512 + 256);
    }
    conv1x1_mma<false, false, false><<<dim3(8, 32), 256>>>(
        A, nullptr, Bb, enc_out_w, enc_out_b, nullptr);     // z -> Bb

    // ---- VQ ----
    cnorm_k<<<8, 256>>>(codebook);
    vq_assign_k<<<dim3(256, 4), 128>>>(Bb, codebook);
    vq_gather_k<<<8192, 256>>>(Bb, codebook, A);            // quant -> A
    vq_counts_k<<<128, 256>>>();

    // ---- Decoder ----
    conv3x3_mma<false, false><<<dim3(8, 32), 256>>>(A, Bb, dec_in_w, dec_in_b, nullptr);
    for (int i = 0; i < 4; ++i) {
        conv3x3_mma<true, true><<<dim3(8, 32), 256>>>(
            Bb, Cc, dec_res_w3 + (size_t)i * 36864, dec_res_b3 + i * 64,
            dec_res_bn + i * 512);
        conv1x1_mma<true, true, true><<<dim3(8, 32), 256>>>(
            Cc, Bb, Bb, dec_res_w1 + (size_t)i * 4096, dec_res_b1 + i * 64,
            dec_res_bn + i * 512 + 256);
    }
    convt_t<64, 64,  2, true,  false><<<dim3(32, 32),  256>>>(Bb, A,   dt_w1, dt_b1, nullptr);
    convt_t<64, 128, 1, false, false><<<dim3(128, 32), 256>>>(A,  Bb,  dt_w2, dt_b2, nullptr);
    convt_t<15, 256, 2, false, true ><<<dim3(128, 32), 256>>>(Bb, out, dt_w3, dt_b3, x);

    finalize_k<<<1, 256>>>(out + (out_size - 2));
}

// round 16
// speedup vs baseline: 1.2537x; 1.2537x over previous
#include <cuda_runtime.h>
#include <math.h>

typedef unsigned long long u64;

// ---------------- packed f32x2 helpers (Blackwell FFMA2 path) ----------------
__device__ __forceinline__ void ffma2(u64 &d, u64 a, u64 b) {
    asm("fma.rn.f32x2 %0, %1, %2, %0;" : "+l"(d) : "l"(a), "l"(b));
}
__device__ __forceinline__ u64 fadd2(u64 a, u64 b) {
    u64 r; asm("add.rn.f32x2 %0, %1, %2;" : "=l"(r) : "l"(a), "l"(b)); return r;
}
__device__ __forceinline__ u64 dup2(float x) {
    u64 r; asm("mov.b64 %0, {%1, %1};" : "=l"(r) : "f"(x)); return r;
}
__device__ __forceinline__ u64 pack2(float lo, float hi) {
    u64 r; asm("mov.b64 %0, {%1, %2};" : "=l"(r) : "f"(lo), "f"(hi)); return r;
}
__device__ __forceinline__ float2 unpk(u64 v) {
    float2 f; asm("mov.b64 {%0, %1}, %2;" : "=f"(f.x), "=f"(f.y) : "l"(v)); return f;
}

// ---------------- tf32 mma helpers ----------------
__device__ __forceinline__ unsigned f2tf(float v) {
    unsigned r; asm("cvt.rna.tf32.f32 %0, %1;" : "=r"(r) : "f"(v)); return r;
}
__device__ __forceinline__ void mma_tf32(
    float &d0, float &d1, float &d2, float &d3,
    unsigned a0, unsigned a1, unsigned a2, unsigned a3,
    unsigned b0, unsigned b1)
{
    asm("mma.sync.aligned.m16n8k8.row.col.f32.tf32.tf32.f32 "
        "{%0,%1,%2,%3}, {%4,%5,%6,%7}, {%8,%9}, {%0,%1,%2,%3};"
        : "+f"(d0), "+f"(d1), "+f"(d2), "+f"(d3)
        : "r"(a0), "r"(a1), "r"(a2), "r"(a3), "r"(b0), "r"(b1));
}

// ---------------- scratch (no allocation allowed) ----------------
__device__ float  g_bufA[32u*64*128*128];
__device__ float  g_bufB[32u*64*128*128];
__device__ float  g_bufC[32u*64*32*32];
__device__ unsigned g_wt[516096];         // pre-transposed tf32 weight bits
__device__ u64    g_best[32768];
__device__ float  g_counts[2048];
__device__ float  g_cnorm[2048];
__device__ double g_vq_ss;
__device__ double g_recon_ss;

// g_wt layout offsets (in words)
#define WT4_1 0
#define WT4_2 16384
#define WT4_3 81920
#define WT3   147456
#define WT1   479232

// ---------------- helpers ----------------
__device__ __forceinline__ float block_sum(float v) {
    __shared__ float sh[256];
    int t = threadIdx.x;
    sh[t] = v; __syncthreads();
    #pragma unroll
    for (int s = 128; s > 0; s >>= 1) {
        if (t < s) sh[t] += sh[t + s];
        __syncthreads();
    }
    return sh[0];
}

__global__ void init_k() {
    int i = blockIdx.x * 256 + threadIdx.x;
    if (i < 32768) g_best[i] = 0xFFFFFFFFFFFFFFFFull;
    if (i < 2048) g_counts[i] = 0.f;
    if (i == 0) { g_vq_ss = 0.0; g_recon_ss = 0.0; }
}

// ---------------- weight pre-transpose kernels ----------------
// conv4s2 weights -> [chunk][tap16][ci8][co64], tf32 bits
__global__ void wprep4_k(const float* __restrict__ w1,
                         const float* __restrict__ w2,
                         const float* __restrict__ w3) {
    int gid = blockIdx.x * 256 + threadIdx.x;
    if (gid >= 147456) return;
    const float* w; int CIN; int local;
    if (gid < WT4_2)      { w = w1; CIN = 15; local = gid; }
    else if (gid < WT4_3) { w = w2; CIN = 64; local = gid - WT4_2; }
    else                  { w = w3; CIN = 64; local = gid - WT4_3; }
    int chunk = local >> 13, r = local & 8191;
    int row = r >> 6, co = r & 63;
    int tap = row >> 3, ci = row & 7;
    int gci = chunk * 8 + ci;
    float v = (gci < CIN) ? w[(co * CIN + gci) * 16 + tap] : 0.f;
    g_wt[gid] = f2tf(v);
}

// conv3x3 weights (9 layers) -> per layer [chunk8][tap9][ci8][co64]
__global__ void wprep3_k(const float* __restrict__ enc_w3,
                         const float* __restrict__ dec_in_w,
                         const float* __restrict__ dec_w3) {
    int gid = blockIdx.x * 256 + threadIdx.x;
    if (gid >= 331776) return;
    int layer = gid / 36864, r = gid - layer * 36864;
    int chunk = r / 4608, r2 = r - chunk * 4608;
    int row = r2 >> 6, co = r2 & 63;
    int tap = row >> 3, ci = row & 7;
    int gci = chunk * 8 + ci;
    const float* w = (layer < 4) ? enc_w3 + (size_t)layer * 36864
                   : (layer == 4) ? dec_in_w
                   : dec_w3 + (size_t)(layer - 5) * 36864;
    g_wt[WT3 + gid] = f2tf(w[co * 576 + gci * 9 + tap]);
}

// conv1x1 weights (9 layers) -> per layer [ci64][co64]
__global__ void wprep1_k(const float* __restrict__ enc_w1,
                         const float* __restrict__ dec_w1,
                         const float* __restrict__ enc_out_w) {
    int gid = blockIdx.x * 256 + threadIdx.x;
    if (gid >= 36864) return;
    int layer = gid >> 12, r = gid & 4095;
    int ci = r >> 6, co = r & 63;
    const float* w = (layer < 4) ? enc_w1 + (size_t)layer * 4096
                   : (layer < 8) ? dec_w1 + (size_t)(layer - 4) * 4096
                   : enc_out_w;
    g_wt[WT1 + gid] = f2tf(w[co * 64 + ci]);
}

// =====================================================================
// conv k4 s2 p1 -> 64 co, tf32 tensor cores, BN(+ReLU) fused.
// Weights pre-transposed in g_wt; staging = linear coalesced copy.
// =====================================================================
template<int CIN, int OW, bool RELU>
__global__ __launch_bounds__(256) void conv4s2_mma(
    const float* __restrict__ in, float* __restrict__ out,
    const unsigned* __restrict__ wt, const float* __restrict__ bias,
    const float* __restrict__ bnp)
{
    constexpr int R = 128 / OW;
    constexpr int NR = 2 * R + 2;
    constexpr int P = OW + 1;
    constexpr int HIN = OW * 2;
    constexpr int RAW = NR * 2 * P;
    constexpr int CIST = (RAW % 32 <= 8) ? (RAW - RAW % 32 + 8)
                                         : (RAW - RAW % 32 + 40);
    constexpr int WSZ = 16 * 8 * 72;
    extern __shared__ unsigned dsm[];
    unsigned* sW  = dsm;            // [tap16][ci8][co pitch72]
    unsigned* sIn = dsm + WSZ;      // [ci8][CIST] parity-split rows
    const int t = threadIdx.x, lane = t & 31, wid = t >> 5;
    const int mw = wid & 3, nw = wid >> 2;
    const int grp = lane >> 2, tig = lane & 3;
    const int n = blockIdx.y, r0 = blockIdx.x * R;
    const int coW = mw * 16;
    const float* inb = in + (size_t)n * CIN * HIN * HIN;
    float acc[8][4];
    #pragma unroll
    for (int nt = 0; nt < 8; ++nt)
        #pragma unroll
        for (int i = 0; i < 4; ++i) acc[nt][i] = 0.f;

    for (int ci0 = 0; ci0 < CIN; ci0 += 8) {
        __syncthreads();
        for (int i = t; i < 8 * RAW; i += 256) {
            int ci = i / RAW, r2 = i - ci * RAW;
            int rr = r2 / (2 * P), r3 = r2 - rr * 2 * P;
            int p = r3 / P, cc = r3 - p * P;
            int gr = 2 * r0 - 1 + rr, gc = 2 * cc - p;
            int gci = ci0 + ci;
            float v = 0.f;
            if (gci < CIN && (unsigned)gr < (unsigned)HIN && (unsigned)gc < (unsigned)HIN)
                v = inb[(size_t)gci * (HIN * HIN) + gr * HIN + gc];
            sIn[ci * CIST + r2] = f2tf(v);
        }
        {
            const unsigned* wtc = wt + (ci0 >> 3) * 8192;
            for (int i = t; i < 8192; i += 256)
                sW[(i >> 6) * 72 + (i & 63)] = wtc[i];
        }
        __syncthreads();
        #pragma unroll
        for (int kh = 0; kh < 4; ++kh) {
            #pragma unroll
            for (int kw = 0; kw < 4; ++kw) {
                const unsigned* wrow = sW + ((kh * 4 + kw) * 8) * 72 + coW + grp;
                unsigned a0 = wrow[tig * 72];
                unsigned a1 = wrow[tig * 72 + 8];
                unsigned a2 = wrow[(tig + 4) * 72];
                unsigned a3 = wrow[(tig + 4) * 72 + 8];
                const int pp = ((kw & 1) ^ 1) * P + (kw >> 1);
                #pragma unroll
                for (int nt = 0; nt < 8; ++nt) {
                    int sidx = nw * 64 + nt * 8;
                    int rowoff = sidx / OW, colb = sidx - rowoff * OW;
                    int idx = (2 * rowoff + kh) * (2 * P) + pp + colb + grp;
                    unsigned b0 = sIn[tig * CIST + idx];
                    unsigned b1 = sIn[(tig + 4) * CIST + idx];
                    mma_tf32(acc[nt][0], acc[nt][1], acc[nt][2], acc[nt][3],
                             a0, a1, a2, a3, b0, b1);
                }
            }
        }
    }
    const int co1 = coW + grp, co2 = co1 + 8;
    float sc1 = bnp[co1] * rsqrtf(bnp[192 + co1] + 1e-5f);
    float sc2 = bnp[co2] * rsqrtf(bnp[192 + co2] + 1e-5f);
    float sh1 = (bias[co1] - bnp[128 + co1]) * sc1 + bnp[64 + co1];
    float sh2 = (bias[co2] - bnp[128 + co2]) * sc2 + bnp[64 + co2];
    float* ob = out + (size_t)n * 64 * (OW * OW);
    #pragma unroll
    for (int nt = 0; nt < 8; ++nt) {
        int sidx = nw * 64 + nt * 8;
        int rowoff = sidx / OW, colb = sidx - rowoff * OW;
        int sp = (r0 + rowoff) * OW + colb + 2 * tig;
        float2 o1, o2;
        o1.x = acc[nt][0] * sc1 + sh1; o1.y = acc[nt][1] * sc1 + sh1;
        o2.x = acc[nt][2] * sc2 + sh2; o2.y = acc[nt][3] * sc2 + sh2;
        if (RELU) {
            o1.x = fmaxf(o1.x, 0.f); o1.y = fmaxf(o1.y, 0.f);
            o2.x = fmaxf(o2.x, 0.f); o2.y = fmaxf(o2.y, 0.f);
        }
        *(float2*)&ob[(size_t)co1 * (OW * OW) + sp] = o1;
        *(float2*)&ob[(size_t)co2 * (OW * OW) + sp] = o2;
    }
}

// =====================================================================
// conv 3x3 s1 p1, 64->64, H=W=32, tf32 tensor cores, prepped weights.
// =====================================================================
template<bool PRERELU, bool HAS_BN>
__global__ __launch_bounds__(256) void conv3x3_mma(
    const float* __restrict__ in, float* __restrict__ out,
    const unsigned* __restrict__ wt, const float* __restrict__ bias,
    const float* __restrict__ bnp)
{
    __shared__ unsigned sIn[8 * 6 * 36];
    __shared__ unsigned sW [9 * 8 * 72];
    const int t = threadIdx.x, lane = t & 31, wid = t >> 5;
    const int mw = wid & 3, nw = wid >> 2;
    const int grp = lane >> 2, tig = lane & 3;
    const int n = blockIdx.y, r0 = blockIdx.x << 2;
    const int coW = mw * 16;
    const float* inb = in + (size_t)n * 64 * 1024;
    float acc[8][4];
    #pragma unroll
    for (int nt = 0; nt < 8; ++nt)
        #pragma unroll
        for (int i = 0; i < 4; ++i) acc[nt][i] = 0.f;

    for (int ci0 = 0; ci0 < 64; ci0 += 8) {
        __syncthreads();
        for (int i = t; i < 8 * 6 * 34; i += 256) {
            int ci = i / 204, r2 = i - ci * 204, rr = r2 / 34, cc = r2 - rr * 34;
            int gr = r0 - 1 + rr, gc = cc - 1;
            float v = 0.f;
            if ((unsigned)gr < 32u && (unsigned)gc < 32u) {
                v = inb[(ci0 + ci) * 1024 + gr * 32 + gc];
                if (PRERELU) v = fmaxf(v, 0.f);
            }
            sIn[ci * 216 + rr * 36 + cc] = f2tf(v);
        }
        {
            const unsigned* wtc = wt + (ci0 >> 3) * 4608;
            for (int i = t; i < 4608; i += 256)
                sW[(i >> 6) * 72 + (i & 63)] = wtc[i];
        }
        __syncthreads();
        #pragma unroll
        for (int kh = 0; kh < 3; ++kh) {
            #pragma unroll
            for (int kw = 0; kw < 3; ++kw) {
                const unsigned* wrow = sW + ((kh * 3 + kw) * 8) * 72 + coW + grp;
                unsigned a0 = wrow[tig * 72];
                unsigned a1 = wrow[tig * 72 + 8];
                unsigned a2 = wrow[(tig + 4) * 72];
                unsigned a3 = wrow[(tig + 4) * 72 + 8];
                #pragma unroll
                for (int nt = 0; nt < 8; ++nt) {
                    int rr = 2 * nw + (nt >> 2) + kh;
                    int cc = (nt & 3) * 8 + grp + kw;
                    unsigned b0 = sIn[tig * 216 + rr * 36 + cc];
                    unsigned b1 = sIn[(tig + 4) * 216 + rr * 36 + cc];
                    mma_tf32(acc[nt][0], acc[nt][1], acc[nt][2], acc[nt][3],
                             a0, a1, a2, a3, b0, b1);
                }
            }
        }
    }
    const int co1 = coW + grp, co2 = co1 + 8;
    float sc1 = 1.f, sc2 = 1.f, sh1 = bias[co1], sh2 = bias[co2];
    if (HAS_BN) {
        sc1 = bnp[co1] * rsqrtf(bnp[192 + co1] + 1e-5f);
        sc2 = bnp[co2] * rsqrtf(bnp[192 + co2] + 1e-5f);
        sh1 = (sh1 - bnp[128 + co1]) * sc1 + bnp[64 + co1];
        sh2 = (sh2 - bnp[128 + co2]) * sc2 + bnp[64 + co2];
    }
    float* ob = out + (size_t)n * 64 * 1024;
    #pragma unroll
    for (int nt = 0; nt < 8; ++nt) {
        int sp = (r0 + 2 * nw + (nt >> 2)) * 32 + (nt & 3) * 8 + 2 * tig;
        float2 o1; o1.x = acc[nt][0] * sc1 + sh1; o1.y = acc[nt][1] * sc1 + sh1;
        float2 o2; o2.x = acc[nt][2] * sc2 + sh2; o2.y = acc[nt][3] * sc2 + sh2;
        *(float2*)&ob[co1 * 1024 + sp] = o1;
        *(float2*)&ob[co2 * 1024 + sp] = o2;
    }
}

// =====================================================================
// conv 1x1, 64->64, HW=1024, tf32 tensor cores, prepped weights.
// =====================================================================
template<bool PRERELU, bool HAS_BN, bool RES>
__global__ __launch_bounds__(256) void conv1x1_mma(
    const float* __restrict__ in, const float* __restrict__ res,
    float* __restrict__ out,
    const unsigned* __restrict__ wt, const float* __restrict__ bias,
    const float* __restrict__ bnp)
{
    __shared__ unsigned sIn[8 * 136];
    __shared__ unsigned sW [64 * 72];
    const int t = threadIdx.x, lane = t & 31, wid = t >> 5;
    const int mw = wid & 3, nw = wid >> 2;
    const int grp = lane >> 2, tig = lane & 3;
    const int n = blockIdx.y, sp0 = blockIdx.x * 128;
    const int coW = mw * 16;
    for (int i = t; i < 4096; i += 256)
        sW[(i >> 6) * 72 + (i & 63)] = wt[i];
    float acc[8][4];
    #pragma unroll
    for (int nt = 0; nt < 8; ++nt)
        #pragma unroll
        for (int i = 0; i < 4; ++i) acc[nt][i] = 0.f;
    const float* inb = in + (size_t)n * 64 * 1024 + sp0;
    for (int ci0 = 0; ci0 < 64; ci0 += 8) {
        __syncthreads();
        for (int i = t; i < 1024; i += 256) {
            int ci = i >> 7, s = i & 127;
            float v = inb[(ci0 + ci) * 1024 + s];
            if (PRERELU) v = fmaxf(v, 0.f);
            sIn[ci * 136 + s] = f2tf(v);
        }
        __syncthreads();
        const unsigned* wrow = sW + ci0 * 72 + coW + grp;
        unsigned a0 = wrow[tig * 72];
        unsigned a1 = wrow[tig * 72 + 8];
        unsigned a2 = wrow[(tig + 4) * 72];
        unsigned a3 = wrow[(tig + 4) * 72 + 8];
        #pragma unroll
        for (int nt = 0; nt < 8; ++nt) {
            int cc = nw * 64 + nt * 8 + grp;
            unsigned b0 = sIn[tig * 136 + cc];
            unsigned b1 = sIn[(tig + 4) * 136 + cc];
            mma_tf32(acc[nt][0], acc[nt][1], acc[nt][2], acc[nt][3],
                     a0, a1, a2, a3, b0, b1);
        }
    }
    const int co1 = coW + grp, co2 = co1 + 8;
    float sc1 = 1.f, sc2 = 1.f, sh1 = bias[co1], sh2 = bias[co2];
    if (HAS_BN) {
        sc1 = bnp[co1] * rsqrtf(bnp[192 + co1] + 1e-5f);
        sc2 = bnp[co2] * rsqrtf(bnp[192 + co2] + 1e-5f);
        sh1 = (sh1 - bnp[128 + co1]) * sc1 + bnp[64 + co1];
        sh2 = (sh2 - bnp[128 + co2]) * sc2 + bnp[64 + co2];
    }
    float* ob = out + (size_t)n * 64 * 1024 + sp0;
    const float* rb = RES ? res + (size_t)n * 64 * 1024 + sp0 : nullptr;
    #pragma unroll
    for (int nt = 0; nt < 8; ++nt) {
        int sp = nw * 64 + nt * 8 + 2 * tig;
        float2 o1; o1.x = acc[nt][0] * sc1 + sh1; o1.y = acc[nt][1] * sc1 + sh1;
        float2 o2; o2.x = acc[nt][2] * sc2 + sh2; o2.y = acc[nt][3] * sc2 + sh2;
        if (RES) {
            float2 r1 = *(const float2*)&rb[co1 * 1024 + sp];
            float2 r2 = *(const float2*)&rb[co2 * 1024 + sp];
            o1.x += r1.x; o1.y += r1.y; o2.x += r2.x; o2.y += r2.y;
        }
        *(float2*)&ob[co1 * 1024 + sp] = o1;
        *(float2*)&ob[co2 * 1024 + sp] = o2;
    }
}

// =====================================================================
// conv-transpose k4 s2 p1, CIN=64. Branch-free 4-tap inner loop. (fp32x2)
// =====================================================================
template<int COUT, int OUTW, int R, bool PRERELU, bool TANH_LOSS>
__global__ __launch_bounds__(256) void convt_t(
    const float* __restrict__ in, float* __restrict__ out,
    const float* __restrict__ w, const float* __restrict__ bias,
    const float* __restrict__ xref)
{
    constexpr int HIN = OUTW / 2;
    constexpr int NRW = R + 1;
    constexpr int NC  = OUTW / 2 + 2;
    constexpr int NCP = (NC & 1) ? NC : NC + 1;
    constexpr int SPT = R * OUTW;
    constexpr int TXN = SPT / 4;
    constexpr int COS = (COUT == 64) ? 64 : 16;
    __shared__ __align__(16) float sIn[8 * NRW * NCP];
    __shared__ __align__(16) float sW [8 * 16 * 68];
    const int t = threadIdx.x, ty = t / TXN, tx = t % TXN;
    const int row = tx / (OUTW / 4), col4 = (tx % (OUTW / 4)) * 4;
    const int n = blockIdx.y, r0 = blockIdx.x * R;
    const int base_hi = ((r0 + 1) >> 1) - 1;
    const float* inb = in + (size_t)n * 64 * HIN * HIN;
    const int ho = r0 + row;
    const int kh_a = (ho + 1) & 1;
    const int rr_a = ((ho + 1) >> 1) - base_hi;
    int cc0[4], kwp[4];
    #pragma unroll
    for (int j = 0; j < 4; ++j) {
        int wo = col4 + j;
        kwp[j] = (wo + 1) & 1;
        cc0[j] = ((wo + 1) >> 1) + 1;
    }
    u64 acc[4][4];
    #pragma unroll
    for (int j = 0; j < 4; ++j)
        #pragma unroll
        for (int p = 0; p < 4; ++p) acc[j][p] = 0ull;

    for (int ci0 = 0; ci0 < 64; ci0 += 8) {
        __syncthreads();
        for (int i = t; i < 8 * NRW * NCP; i += 256) {
            int ci = i / (NRW * NCP), r2 = i - ci * (NRW * NCP);
            int rr = r2 / NCP, cc = r2 - rr * NCP;
            int gr = base_hi + rr, gc = cc - 1;
            float v = 0.f;
            if ((unsigned)gr < (unsigned)HIN && (unsigned)gc < (unsigned)HIN) {
                v = inb[(ci0 + ci) * (HIN * HIN) + gr * HIN + gc];
                if (PRERELU) v = fmaxf(v, 0.f);
            }
            sIn[i] = v;
        }
        for (int i = t; i < 8 * 16 * COS; i += 256) {
            int ci = i / (16 * COS), r2 = i - ci * (16 * COS);
            int co = r2 >> 4, tap = r2 & 15;
            float v = (co < COUT) ? w[((ci0 + ci) * COUT + co) * 16 + tap] : 0.f;
            sW[ci * 1088 + tap * 68 + co] = v;
        }
        __syncthreads();
        #pragma unroll
        for (int ci = 0; ci < 8; ++ci) {
            const float* rA = sIn + ci * (NRW * NCP) + rr_a * NCP;
            const float* rB = rA - NCP;
            const float* sWb = sW + ci * 1088 + ty * 8;
            #pragma unroll
            for (int jp = 0; jp < 2; ++jp) {
                int t0 = kh_a * 4 + kwp[jp];
                u64 wv[4][4];
                #pragma unroll
                for (int k = 0; k < 4; ++k) {
                    int tap = t0 + (k & 1) * 2 + (k >> 1) * 8;
                    const ulonglong2* wp = (const ulonglong2*)(sWb + tap * 68);
                    ulonglong2 wa = wp[0], wb = wp[1];
                    wv[k][0] = wa.x; wv[k][1] = wa.y; wv[k][2] = wb.x; wv[k][3] = wb.y;
                }
                #pragma unroll
                for (int jj = 0; jj < 2; ++jj) {
                    int j = jp + jj * 2;
                    int ca = cc0[j], cb = ca - 1;
                    u64 da = dup2(rA[ca]), db = dup2(rA[cb]);
                    u64 dc = dup2(rB[ca]), dd = dup2(rB[cb]);
                    #pragma unroll
                    for (int p = 0; p < 4; ++p) {
                        ffma2(acc[j][p], da, wv[0][p]);
                        ffma2(acc[j][p], db, wv[1][p]);
                        ffma2(acc[j][p], dc, wv[2][p]);
                        ffma2(acc[j][p], dd, wv[3][p]);
                    }
                }
            }
        }
    }
    float ls = 0.f;
    #pragma unroll
    for (int p = 0; p < 4; ++p) {
        float rr2[2][4];
        #pragma unroll
        for (int j = 0; j < 4; ++j) {
            float2 ff = unpk(acc[j][p]);
            rr2[0][j] = ff.x; rr2[1][j] = ff.y;
        }
        #pragma unroll
        for (int l = 0; l < 2; ++l) {
            int co = ty * 8 + 2 * p + l;
            if (co < COUT) {
                float b = bias[co];
                size_t oi = ((size_t)n * COUT + co) * ((size_t)OUTW * OUTW) + ho * OUTW + col4;
                float r[4];
                #pragma unroll
                for (int j = 0; j < 4; ++j) {
                    r[j] = rr2[l][j] + b;
                    if (TANH_LOSS) {
                        r[j] = tanhf(r[j]);
                        float d = r[j] - xref[oi + j];
                        ls += d * d;
                    } else {
                        r[j] = fmaxf(r[j], 0.f);
                    }
                }
                float4 o; o.x = r[0]; o.y = r[1]; o.z = r[2]; o.w = r[3];
                *(float4*)&out[oi] = o;
            }
        }
    }
    if (TANH_LOSS) {
        float s = block_sum(ls);
        if (t == 0) atomicAdd(&g_recon_ss, (double)s);
    }
}

// ---------------- VQ ----------------
__global__ void cnorm_k(const float* __restrict__ cb) {
    int k = blockIdx.x * 256 + threadIdx.x;
    if (k < 2048) {
        float s = 0.f;
        #pragma unroll
        for (int d = 0; d < 64; ++d) { float c = cb[k * 64 + d]; s += c * c; }
        g_cnorm[k] = s;
    }
}

__global__ __launch_bounds__(128) void vq_assign_k(
    const float* __restrict__ z, const float* __restrict__ cb)
{
    __shared__ __align__(16) float4 sc[128 * 16];
    __shared__ float  sn[128];
    const int row = blockIdx.x * 128 + threadIdx.x;
    const int q0 = blockIdx.y * 512;
    const int b = row >> 10, hw = row & 1023;
    u64 zr2[32];
    const float* zp = z + ((size_t)b * 64) * 1024 + hw;
    #pragma unroll
    for (int d2 = 0; d2 < 32; ++d2)
        zr2[d2] = pack2(zp[(2 * d2) * 1024], zp[(2 * d2 + 1) * 1024]);
    float best = 3.4e38f; int bi = 0;
    const float4* cb4 = (const float4*)cb;
    for (int k0 = q0; k0 < q0 + 512; k0 += 128) {
        __syncthreads();
        for (int i = threadIdx.x; i < 128 * 16; i += 128) sc[i] = cb4[k0 * 16 + i];
        sn[threadIdx.x] = g_cnorm[k0 + threadIdx.x];
        __syncthreads();
        for (int kk = 0; kk < 128; ++kk) {
            const ulonglong2* cp = (const ulonglong2*)(sc + kk * 16);
            u64 a0 = 0ull, a1 = 0ull, a2 = 0ull, a3 = 0ull;
            #pragma unroll
            for (int j = 0; j < 8; ++j) {
                ulonglong2 c0 = cp[2 * j], c1 = cp[2 * j + 1];
                ffma2(a0, zr2[4 * j + 0], c0.x);
                ffma2(a1, zr2[4 * j + 1], c0.y);
                ffma2(a2, zr2[4 * j + 2], c1.x);
                ffma2(a3, zr2[4 * j + 3], c1.y);
            }
            u64 s2 = fadd2(fadd2(a0, a1), fadd2(a2, a3));
            float2 f = unpk(s2);
            float dist = sn[kk] - 2.f * (f.x + f.y);
            if (dist < best) { best = dist; bi = k0 + kk; }
        }
    }
    unsigned int fb = __float_as_uint(best);
    unsigned int key = fb ^ (((int)fb >> 31) | 0x80000000u);
    u64 packed = ((u64)key << 32) | (unsigned)bi;
    atomicMin(&g_best[row], packed);
}

__global__ __launch_bounds__(256) void vq_gather_k(
    const float* __restrict__ z, const float* __restrict__ cb,
    float* __restrict__ quant)
{
    int gid = blockIdx.x * 256 + threadIdx.x;
    int b = gid >> 16;
    int rem = gid & 65535;
    int d = rem >> 10;
    int hw = rem & 1023;
    int k = (int)(unsigned)(g_best[(b << 10) + hw] & 0xFFFFFFFFull);
    float q = cb[k * 64 + d];
    float zv = z[gid];
    quant[gid] = q;
    float diff = q - zv;
    float s = block_sum(diff * diff);
    if (threadIdx.x == 0) atomicAdd(&g_vq_ss, (double)s);
}

__global__ void vq_counts_k() {
    int i = blockIdx.x * 256 + threadIdx.x;
    if (i < 32768) {
        int k = (int)(unsigned)(g_best[i] & 0xFFFFFFFFull);
        atomicAdd(&g_counts[k], 1.0f);
    }
}

// ---------------- finalize ----------------
__global__ void finalize_k(float* __restrict__ out2) {
    float s = 0.f;
    for (int k = threadIdx.x; k < 2048; k += 256) {
        float p = g_counts[k] * (1.0f / 32768.0f);
        s += p * logf(p + 1e-10f);
    }
    float tot = block_sum(s);
    if (threadIdx.x == 0) {
        float perp = expf(-tot);
        float loss = (float)(g_recon_ss / 31457280.0 + 1.25 * (g_vq_ss / 2097152.0));
        out2[0] = loss;
        out2[1] = perp;
    }
}

// ---------------- launcher ----------------
extern "C" void kernel_launch(void* const* d_in, const int* in_sizes, int n_in,
                              void* d_out, int out_size) {
    const float* x          = (const float*)d_in[0];
    const float* ew1        = (const float*)d_in[1];
    const float* eb1        = (const float*)d_in[2];
    const float* ew2        = (const float*)d_in[3];
    const float* eb2        = (const float*)d_in[4];
    const float* ew3        = (const float*)d_in[5];
    const float* eb3        = (const float*)d_in[6];
    const float* enc_bn     = (const float*)d_in[7];
    const float* enc_res_w3 = (const float*)d_in[8];
    const float* enc_res_b3 = (const float*)d_in[9];
    const float* enc_res_w1 = (const float*)d_in[10];
    const float* enc_res_b1 = (const float*)d_in[11];
    const float* enc_res_bn = (const float*)d_in[12];
    const float* enc_out_w  = (const float*)d_in[13];
    const float* enc_out_b  = (const float*)d_in[14];
    const float* codebook   = (const float*)d_in[15];
    const float* dec_in_w   = (const float*)d_in[16];
    const float* dec_in_b   = (const float*)d_in[17];
    const float* dec_res_w3 = (const float*)d_in[18];
    const float* dec_res_b3 = (const float*)d_in[19];
    const float* dec_res_w1 = (const float*)d_in[20];
    const float* dec_res_b1 = (const float*)d_in[21];
    const float* dec_res_bn = (const float*)d_in[22];
    const float* dt_w1      = (const float*)d_in[23];
    const float* dt_b1      = (const float*)d_in[24];
    const float* dt_w2      = (const float*)d_in[25];
    const float* dt_b2      = (const float*)d_in[26];
    const float* dt_w3      = (const float*)d_in[27];
    const float* dt_b3      = (const float*)d_in[28];

    void *pa, *pb, *pc, *pw;
    cudaGetSymbolAddress(&pa, g_bufA);
    cudaGetSymbolAddress(&pb, g_bufB);
    cudaGetSymbolAddress(&pc, g_bufC);
    cudaGetSymbolAddress(&pw, g_wt);
    float* A  = (float*)pa;
    float* Bb = (float*)pb;
    float* Cc = (float*)pc;
    const unsigned* W = (const unsigned*)pw;
    float* out = (float*)d_out;

    // dynamic SMEM sizes: 16*8*72 weights + 8*CIST input (u32 words)
    const int smem1 = (16 * 8 * 72 + 8 * 1032) * 4;   // OW=128
    const int smem2 = (16 * 8 * 72 + 8 * 808)  * 4;   // OW=64
    const int smem3 = (16 * 8 * 72 + 8 * 680)  * 4;   // OW=32
    cudaFuncSetAttribute(conv4s2_mma<15, 128, true >,
                         cudaFuncAttributeMaxDynamicSharedMemorySize, smem1);
    cudaFuncSetAttribute(conv4s2_mma<64, 64, true >,
                         cudaFuncAttributeMaxDynamicSharedMemorySize, smem2);
    cudaFuncSetAttribute(conv4s2_mma<64, 32, false>,
                         cudaFuncAttributeMaxDynamicSharedMemorySize, smem3);

    init_k<<<128, 256>>>();
    wprep4_k<<<576, 256>>>(ew1, ew2, ew3);
    wprep3_k<<<1296, 256>>>(enc_res_w3, dec_in_w, dec_res_w3);
    wprep1_k<<<144, 256>>>(enc_res_w1, dec_res_w1, enc_out_w);

    // ---- Encoder ----
    conv4s2_mma<15, 128, true ><<<dim3(128, 32), 256, smem1>>>(x,  A,  W + WT4_1, eb1, enc_bn);
    conv4s2_mma<64, 64,  true ><<<dim3(32, 32),  256, smem2>>>(A,  Bb, W + WT4_2, eb2, enc_bn + 256);
    conv4s2_mma<64, 32,  false><<<dim3(8, 32),   256, smem3>>>(Bb, A,  W + WT4_3, eb3, enc_bn + 512);
    for (int i = 0; i < 4; ++i) {
        conv3x3_mma<true, true><<<dim3(8, 32), 256>>>(
            A, Bb, W + WT3 + i * 36864, enc_res_b3 + i * 64,
            enc_res_bn + i * 512);
        conv1x1_mma<true, true, true><<<dim3(8, 32), 256>>>(
            Bb, A, A, W + WT1 + i * 4096, enc_res_b1 + i * 64,
            enc_res_bn + i * 512 + 256);
    }
    conv1x1_mma<false, false, false><<<dim3(8, 32), 256>>>(
        A, nullptr, Bb, W + WT1 + 8 * 4096, enc_out_b, nullptr);   // z -> Bb

    // ---- VQ ----
    cnorm_k<<<8, 256>>>(codebook);
    vq_assign_k<<<dim3(256, 4), 128>>>(Bb, codebook);
    vq_gather_k<<<8192, 256>>>(Bb, codebook, A);            // quant -> A
    vq_counts_k<<<128, 256>>>();

    // ---- Decoder ----
    conv3x3_mma<false, false><<<dim3(8, 32), 256>>>(
        A, Bb, W + WT3 + 4 * 36864, dec_in_b, nullptr);
    for (int i = 0; i < 4; ++i) {
        conv3x3_mma<true, true><<<dim3(8, 32), 256>>>(
            Bb, Cc, W + WT3 + (5 + i) * 36864, dec_res_b3 + i * 64,
            dec_res_bn + i * 512);
        conv1x1_mma<true, true, true><<<dim3(8, 32), 256>>>(
            Cc, Bb, Bb, W + WT1 + (4 + i) * 4096, dec_res_b1 + i * 64,
            dec_res_bn + i * 512 + 256);
    }
    convt_t<64, 64,  2, true,  false><<<dim3(32, 32),  256>>>(Bb, A,   dt_w1, dt_b1, nullptr);
    convt_t<64, 128, 1, false, false><<<dim3(128, 32), 256>>>(A,  Bb,  dt_w2, dt_b2, nullptr);
    convt_t<15, 256, 2, false, true ><<<dim3(128, 32), 256>>>(Bb, out, dt_w3, dt_b3, x);

    finalize_k<<<1, 256>>>(out + (out_size - 2));
}

// round 17
// speedup vs baseline: 1.5989x; 1.2754x over previous
#include <cuda_runtime.h>
#include <math.h>

typedef unsigned long long u64;

// ---------------- packed f32x2 helpers ----------------
__device__ __forceinline__ u64 pack2(float lo, float hi) {
    u64 r; asm("mov.b64 %0, {%1, %2};" : "=l"(r) : "f"(lo), "f"(hi)); return r;
}
__device__ __forceinline__ void ffma2(u64 &d, u64 a, u64 b) {
    asm("fma.rn.f32x2 %0, %1, %2, %0;" : "+l"(d) : "l"(a), "l"(b));
}
__device__ __forceinline__ u64 fadd2(u64 a, u64 b) {
    u64 r; asm("add.rn.f32x2 %0, %1, %2;" : "=l"(r) : "l"(a), "l"(b)); return r;
}
__device__ __forceinline__ float2 unpk(u64 v) {
    float2 f; asm("mov.b64 {%0, %1}, %2;" : "=f"(f.x), "=f"(f.y) : "l"(v)); return f;
}

// ---------------- tf32 mma helpers ----------------
__device__ __forceinline__ unsigned f2tf(float v) {
    unsigned r; asm("cvt.rna.tf32.f32 %0, %1;" : "=r"(r) : "f"(v)); return r;
}
__device__ __forceinline__ void mma_tf32(
    float &d0, float &d1, float &d2, float &d3,
    unsigned a0, unsigned a1, unsigned a2, unsigned a3,
    unsigned b0, unsigned b1)
{
    asm("mma.sync.aligned.m16n8k8.row.col.f32.tf32.tf32.f32 "
        "{%0,%1,%2,%3}, {%4,%5,%6,%7}, {%8,%9}, {%0,%1,%2,%3};"
        : "+f"(d0), "+f"(d1), "+f"(d2), "+f"(d3)
        : "r"(a0), "r"(a1), "r"(a2), "r"(a3), "r"(b0), "r"(b1));
}

// ---------------- scratch (no allocation allowed) ----------------
__device__ float  g_bufA[32u*64*128*128];
__device__ float  g_bufB[32u*64*128*128];
__device__ float  g_bufC[32u*64*32*32];
__device__ unsigned g_wt[712704];         // pre-transposed tf32 weight bits
__device__ u64    g_best[32768];
__device__ float  g_counts[2048];
__device__ float  g_cnorm[2048];
__device__ double g_vq_ss;
__device__ double g_recon_ss;

// g_wt layout offsets (in words)
#define WT4_1 0
#define WT4_2 16384
#define WT4_3 81920
#define WT3   147456
#define WT1   479232
#define WTT1  516096
#define WTT2  581632
#define WTT3  647168

// ---------------- helpers ----------------
__device__ __forceinline__ float block_sum(float v) {
    __shared__ float sh[256];
    int t = threadIdx.x;
    sh[t] = v; __syncthreads();
    #pragma unroll
    for (int s = 128; s > 0; s >>= 1) {
        if (t < s) sh[t] += sh[t + s];
        __syncthreads();
    }
    return sh[0];
}

__global__ void init_k() {
    int i = blockIdx.x * 256 + threadIdx.x;
    if (i < 32768) g_best[i] = 0xFFFFFFFFFFFFFFFFull;
    if (i < 2048) g_counts[i] = 0.f;
    if (i == 0) { g_vq_ss = 0.0; g_recon_ss = 0.0; }
}

// ---------------- weight pre-transpose kernels ----------------
__global__ void wprep4_k(const float* __restrict__ w1,
                         const float* __restrict__ w2,
                         const float* __restrict__ w3) {
    int gid = blockIdx.x * 256 + threadIdx.x;
    if (gid >= 147456) return;
    const float* w; int CIN; int local;
    if (gid < WT4_2)      { w = w1; CIN = 15; local = gid; }
    else if (gid < WT4_3) { w = w2; CIN = 64; local = gid - WT4_2; }
    else                  { w = w3; CIN = 64; local = gid - WT4_3; }
    int chunk = local >> 13, r = local & 8191;
    int row = r >> 6, co = r & 63;
    int tap = row >> 3, ci = row & 7;
    int gci = chunk * 8 + ci;
    float v = (gci < CIN) ? w[(co * CIN + gci) * 16 + tap] : 0.f;
    g_wt[gid] = f2tf(v);
}

__global__ void wprep3_k(const float* __restrict__ enc_w3,
                         const float* __restrict__ dec_in_w,
                         const float* __restrict__ dec_w3) {
    int gid = blockIdx.x * 256 + threadIdx.x;
    if (gid >= 331776) return;
    int layer = gid / 36864, r = gid - layer * 36864;
    int chunk = r / 4608, r2 = r - chunk * 4608;
    int row = r2 >> 6, co = r2 & 63;
    int tap = row >> 3, ci = row & 7;
    int gci = chunk * 8 + ci;
    const float* w = (layer < 4) ? enc_w3 + (size_t)layer * 36864
                   : (layer == 4) ? dec_in_w
                   : dec_w3 + (size_t)(layer - 5) * 36864;
    g_wt[WT3 + gid] = f2tf(w[co * 576 + gci * 9 + tap]);
}

__global__ void wprep1_k(const float* __restrict__ enc_w1,
                         const float* __restrict__ dec_w1,
                         const float* __restrict__ enc_out_w) {
    int gid = blockIdx.x * 256 + threadIdx.x;
    if (gid >= 36864) return;
    int layer = gid >> 12, r = gid & 4095;
    int ci = r >> 6, co = r & 63;
    const float* w = (layer < 4) ? enc_w1 + (size_t)layer * 4096
                   : (layer < 8) ? dec_w1 + (size_t)(layer - 4) * 4096
                   : enc_out_w;
    g_wt[WT1 + gid] = f2tf(w[co * 64 + ci]);
}

// convT weights: per layer [ph2][chunk8][pw2][tap4][ci8][co64]
__global__ void wprepT_k(const float* __restrict__ w1,
                         const float* __restrict__ w2,
                         const float* __restrict__ w3) {
    int gid = blockIdx.x * 256 + threadIdx.x;
    if (gid >= 196608) return;
    int layer = gid >> 16, local = gid & 65535;
    const float* w = (layer == 0) ? w1 : (layer == 1) ? w2 : w3;
    int COUT = (layer == 2) ? 15 : 64;
    int ph = local >> 15, r = local & 32767;
    int chunk = r >> 12, r2 = r & 4095;
    int pw = r2 >> 11, r3 = r2 & 2047;
    int tp = r3 >> 9, ci = (r3 >> 6) & 7, co = r3 & 63;
    int dh = tp >> 1, dw = tp & 1;
    int kh = 2 - 2 * dh + (1 - ph);
    int kw = 2 - 2 * dw + (1 - pw);
    int gci = chunk * 8 + ci;
    float v = (co < COUT) ? w[(gci * COUT + co) * 16 + kh * 4 + kw] : 0.f;
    g_wt[WTT1 + gid] = f2tf(v);
}

// =====================================================================
// conv k4 s2 p1 -> 64 co, tf32 tensor cores, BN(+ReLU) fused.
// =====================================================================
template<int CIN, int OW, bool RELU>
__global__ __launch_bounds__(256) void conv4s2_mma(
    const float* __restrict__ in, float* __restrict__ out,
    const unsigned* __restrict__ wt, const float* __restrict__ bias,
    const float* __restrict__ bnp)
{
    constexpr int R = 128 / OW;
    constexpr int NR = 2 * R + 2;
    constexpr int P = OW + 1;
    constexpr int HIN = OW * 2;
    constexpr int RAW = NR * 2 * P;
    constexpr int CIST = (RAW % 32 <= 8) ? (RAW - RAW % 32 + 8)
                                         : (RAW - RAW % 32 + 40);
    constexpr int WSZ = 16 * 8 * 72;
    extern __shared__ unsigned dsm[];
    unsigned* sW  = dsm;
    unsigned* sIn = dsm + WSZ;
    const int t = threadIdx.x, lane = t & 31, wid = t >> 5;
    const int mw = wid & 3, nw = wid >> 2;
    const int grp = lane >> 2, tig = lane & 3;
    const int n = blockIdx.y, r0 = blockIdx.x * R;
    const int coW = mw * 16;
    const float* inb = in + (size_t)n * CIN * HIN * HIN;
    float acc[8][4];
    #pragma unroll
    for (int nt = 0; nt < 8; ++nt)
        #pragma unroll
        for (int i = 0; i < 4; ++i) acc[nt][i] = 0.f;

    for (int ci0 = 0; ci0 < CIN; ci0 += 8) {
        __syncthreads();
        for (int i = t; i < 8 * RAW; i += 256) {
            int ci = i / RAW, r2 = i - ci * RAW;
            int rr = r2 / (2 * P), r3 = r2 - rr * 2 * P;
            int p = r3 / P, cc = r3 - p * P;
            int gr = 2 * r0 - 1 + rr, gc = 2 * cc - p;
            int gci = ci0 + ci;
            float v = 0.f;
            if (gci < CIN && (unsigned)gr < (unsigned)HIN && (unsigned)gc < (unsigned)HIN)
                v = inb[(size_t)gci * (HIN * HIN) + gr * HIN + gc];
            sIn[ci * CIST + r2] = f2tf(v);
        }
        {
            const unsigned* wtc = wt + (ci0 >> 3) * 8192;
            for (int i = t; i < 8192; i += 256)
                sW[(i >> 6) * 72 + (i & 63)] = wtc[i];
        }
        __syncthreads();
        #pragma unroll
        for (int kh = 0; kh < 4; ++kh) {
            #pragma unroll
            for (int kw = 0; kw < 4; ++kw) {
                const unsigned* wrow = sW + ((kh * 4 + kw) * 8) * 72 + coW + grp;
                unsigned a0 = wrow[tig * 72];
                unsigned a1 = wrow[tig * 72 + 8];
                unsigned a2 = wrow[(tig + 4) * 72];
                unsigned a3 = wrow[(tig + 4) * 72 + 8];
                const int pp = ((kw & 1) ^ 1) * P + (kw >> 1);
                #pragma unroll
                for (int nt = 0; nt < 8; ++nt) {
                    int sidx = nw * 64 + nt * 8;
                    int rowoff = sidx / OW, colb = sidx - rowoff * OW;
                    int idx = (2 * rowoff + kh) * (2 * P) + pp + colb + grp;
                    unsigned b0 = sIn[tig * CIST + idx];
                    unsigned b1 = sIn[(tig + 4) * CIST + idx];
                    mma_tf32(acc[nt][0], acc[nt][1], acc[nt][2], acc[nt][3],
                             a0, a1, a2, a3, b0, b1);
                }
            }
        }
    }
    const int co1 = coW + grp, co2 = co1 + 8;
    float sc1 = bnp[co1] * rsqrtf(bnp[192 + co1] + 1e-5f);
    float sc2 = bnp[co2] * rsqrtf(bnp[192 + co2] + 1e-5f);
    float sh1 = (bias[co1] - bnp[128 + co1]) * sc1 + bnp[64 + co1];
    float sh2 = (bias[co2] - bnp[128 + co2]) * sc2 + bnp[64 + co2];
    float* ob = out + (size_t)n * 64 * (OW * OW);
    #pragma unroll
    for (int nt = 0; nt < 8; ++nt) {
        int sidx = nw * 64 + nt * 8;
        int rowoff = sidx / OW, colb = sidx - rowoff * OW;
        int sp = (r0 + rowoff) * OW + colb + 2 * tig;
        float2 o1, o2;
        o1.x = acc[nt][0] * sc1 + sh1; o1.y = acc[nt][1] * sc1 + sh1;
        o2.x = acc[nt][2] * sc2 + sh2; o2.y = acc[nt][3] * sc2 + sh2;
        if (RELU) {
            o1.x = fmaxf(o1.x, 0.f); o1.y = fmaxf(o1.y, 0.f);
            o2.x = fmaxf(o2.x, 0.f); o2.y = fmaxf(o2.y, 0.f);
        }
        *(float2*)&ob[(size_t)co1 * (OW * OW) + sp] = o1;
        *(float2*)&ob[(size_t)co2 * (OW * OW) + sp] = o2;
    }
}

// =====================================================================
// conv 3x3 s1 p1, 64->64, H=W=32, tf32 tensor cores, prepped weights.
// =====================================================================
template<bool PRERELU, bool HAS_BN>
__global__ __launch_bounds__(256) void conv3x3_mma(
    const float* __restrict__ in, float* __restrict__ out,
    const unsigned* __restrict__ wt, const float* __restrict__ bias,
    const float* __restrict__ bnp)
{
    __shared__ unsigned sIn[8 * 6 * 36];
    __shared__ unsigned sW [9 * 8 * 72];
    const int t = threadIdx.x, lane = t & 31, wid = t >> 5;
    const int mw = wid & 3, nw = wid >> 2;
    const int grp = lane >> 2, tig = lane & 3;
    const int n = blockIdx.y, r0 = blockIdx.x << 2;
    const int coW = mw * 16;
    const float* inb = in + (size_t)n * 64 * 1024;
    float acc[8][4];
    #pragma unroll
    for (int nt = 0; nt < 8; ++nt)
        #pragma unroll
        for (int i = 0; i < 4; ++i) acc[nt][i] = 0.f;

    for (int ci0 = 0; ci0 < 64; ci0 += 8) {
        __syncthreads();
        for (int i = t; i < 8 * 6 * 34; i += 256) {
            int ci = i / 204, r2 = i - ci * 204, rr = r2 / 34, cc = r2 - rr * 34;
            int gr = r0 - 1 + rr, gc = cc - 1;
            float v = 0.f;
            if ((unsigned)gr < 32u && (unsigned)gc < 32u) {
                v = inb[(ci0 + ci) * 1024 + gr * 32 + gc];
                if (PRERELU) v = fmaxf(v, 0.f);
            }
            sIn[ci * 216 + rr * 36 + cc] = f2tf(v);
        }
        {
            const unsigned* wtc = wt + (ci0 >> 3) * 4608;
            for (int i = t; i < 4608; i += 256)
                sW[(i >> 6) * 72 + (i & 63)] = wtc[i];
        }
        __syncthreads();
        #pragma unroll
        for (int kh = 0; kh < 3; ++kh) {
            #pragma unroll
            for (int kw = 0; kw < 3; ++kw) {
                const unsigned* wrow = sW + ((kh * 3 + kw) * 8) * 72 + coW + grp;
                unsigned a0 = wrow[tig * 72];
                unsigned a1 = wrow[tig * 72 + 8];
                unsigned a2 = wrow[(tig + 4) * 72];
                unsigned a3 = wrow[(tig + 4) * 72 + 8];
                #pragma unroll
                for (int nt = 0; nt < 8; ++nt) {
                    int rr = 2 * nw + (nt >> 2) + kh;
                    int cc = (nt & 3) * 8 + grp + kw;
                    unsigned b0 = sIn[tig * 216 + rr * 36 + cc];
                    unsigned b1 = sIn[(tig + 4) * 216 + rr * 36 + cc];
                    mma_tf32(acc[nt][0], acc[nt][1], acc[nt][2], acc[nt][3],
                             a0, a1, a2, a3, b0, b1);
                }
            }
        }
    }
    const int co1 = coW + grp, co2 = co1 + 8;
    float sc1 = 1.f, sc2 = 1.f, sh1 = bias[co1], sh2 = bias[co2];
    if (HAS_BN) {
        sc1 = bnp[co1] * rsqrtf(bnp[192 + co1] + 1e-5f);
        sc2 = bnp[co2] * rsqrtf(bnp[192 + co2] + 1e-5f);
        sh1 = (sh1 - bnp[128 + co1]) * sc1 + bnp[64 + co1];
        sh2 = (sh2 - bnp[128 + co2]) * sc2 + bnp[64 + co2];
    }
    float* ob = out + (size_t)n * 64 * 1024;
    #pragma unroll
    for (int nt = 0; nt < 8; ++nt) {
        int sp = (r0 + 2 * nw + (nt >> 2)) * 32 + (nt & 3) * 8 + 2 * tig;
        float2 o1; o1.x = acc[nt][0] * sc1 + sh1; o1.y = acc[nt][1] * sc1 + sh1;
        float2 o2; o2.x = acc[nt][2] * sc2 + sh2; o2.y = acc[nt][3] * sc2 + sh2;
        *(float2*)&ob[co1 * 1024 + sp] = o1;
        *(float2*)&ob[co2 * 1024 + sp] = o2;
    }
}

// =====================================================================
// conv 1x1, 64->64, HW=1024, tf32 tensor cores, prepped weights.
// =====================================================================
template<bool PRERELU, bool HAS_BN, bool RES>
__global__ __launch_bounds__(256) void conv1x1_mma(
    const float* __restrict__ in, const float* __restrict__ res,
    float* __restrict__ out,
    const unsigned* __restrict__ wt, const float* __restrict__ bias,
    const float* __restrict__ bnp)
{
    __shared__ unsigned sIn[8 * 136];
    __shared__ unsigned sW [64 * 72];
    const int t = threadIdx.x, lane = t & 31, wid = t >> 5;
    const int mw = wid & 3, nw = wid >> 2;
    const int grp = lane >> 2, tig = lane & 3;
    const int n = blockIdx.y, sp0 = blockIdx.x * 128;
    const int coW = mw * 16;
    for (int i = t; i < 4096; i += 256)
        sW[(i >> 6) * 72 + (i & 63)] = wt[i];
    float acc[8][4];
    #pragma unroll
    for (int nt = 0; nt < 8; ++nt)
        #pragma unroll
        for (int i = 0; i < 4; ++i) acc[nt][i] = 0.f;
    const float* inb = in + (size_t)n * 64 * 1024 + sp0;
    for (int ci0 = 0; ci0 < 64; ci0 += 8) {
        __syncthreads();
        for (int i = t; i < 1024; i += 256) {
            int ci = i >> 7, s = i & 127;
            float v = inb[(ci0 + ci) * 1024 + s];
            if (PRERELU) v = fmaxf(v, 0.f);
            sIn[ci * 136 + s] = f2tf(v);
        }
        __syncthreads();
        const unsigned* wrow = sW + ci0 * 72 + coW + grp;
        unsigned a0 = wrow[tig * 72];
        unsigned a1 = wrow[tig * 72 + 8];
        unsigned a2 = wrow[(tig + 4) * 72];
        unsigned a3 = wrow[(tig + 4) * 72 + 8];
        #pragma unroll
        for (int nt = 0; nt < 8; ++nt) {
            int cc = nw * 64 + nt * 8 + grp;
            unsigned b0 = sIn[tig * 136 + cc];
            unsigned b1 = sIn[(tig + 4) * 136 + cc];
            mma_tf32(acc[nt][0], acc[nt][1], acc[nt][2], acc[nt][3],
                     a0, a1, a2, a3, b0, b1);
        }
    }
    const int co1 = coW + grp, co2 = co1 + 8;
    float sc1 = 1.f, sc2 = 1.f, sh1 = bias[co1], sh2 = bias[co2];
    if (HAS_BN) {
        sc1 = bnp[co1] * rsqrtf(bnp[192 + co1] + 1e-5f);
        sc2 = bnp[co2] * rsqrtf(bnp[192 + co2] + 1e-5f);
        sh1 = (sh1 - bnp[128 + co1]) * sc1 + bnp[64 + co1];
        sh2 = (sh2 - bnp[128 + co2]) * sc2 + bnp[64 + co2];
    }
    float* ob = out + (size_t)n * 64 * 1024 + sp0;
    const float* rb = RES ? res + (size_t)n * 64 * 1024 + sp0 : nullptr;
    #pragma unroll
    for (int nt = 0; nt < 8; ++nt) {
        int sp = nw * 64 + nt * 8 + 2 * tig;
        float2 o1; o1.x = acc[nt][0] * sc1 + sh1; o1.y = acc[nt][1] * sc1 + sh1;
        float2 o2; o2.x = acc[nt][2] * sc2 + sh2; o2.y = acc[nt][3] * sc2 + sh2;
        if (RES) {
            float2 r1 = *(const float2*)&rb[co1 * 1024 + sp];
            float2 r2 = *(const float2*)&rb[co2 * 1024 + sp];
            o1.x += r1.x; o1.y += r1.y; o2.x += r2.x; o2.y += r2.y;
        }
        *(float2*)&ob[co1 * 1024 + sp] = o1;
        *(float2*)&ob[co2 * 1024 + sp] = o2;
    }
}

// =====================================================================
// conv-transpose k4 s2 p1 via parity decomposition, tf32 tensor cores.
// Block = one ph class, BOTH pw classes (dense float2 stores).
// Warp = 16 co x 32 class-cols x 2 pw (COUT=64) or 16 co-slot x 32 x 2.
// =====================================================================
template<int COUT, int OUTW, bool PRERELU, bool TANH_LOSS>
__global__ __launch_bounds__(256) void convt_mma(
    const float* __restrict__ in, float* __restrict__ out,
    const unsigned* __restrict__ wt, const float* __restrict__ bias,
    const float* __restrict__ xref)
{
    constexpr int HIN = OUTW / 2, CW = HIN;
    constexpr int NSP = (COUT == 64) ? 64 : 256;   // class outputs per block per pw
    constexpr int TR = (NSP / CW > 0) ? NSP / CW : 1;
    constexpr int NRW = TR + 1;
    constexpr int CP = HIN + 3;                    // staged cols (HIN+2, odd-padded)
    constexpr int CIS0 = NRW * CP;
    constexpr int CIS = CIS0 + ((8 - (CIS0 % 32)) + 32) % 32;   // ≡8 mod 32
    __shared__ unsigned sIn[8 * CIS];
    __shared__ unsigned sW [64 * 72];              // [pw2][tap4][ci8] rows
    const int t = threadIdx.x, lane = t & 31, wid = t >> 5;
    const int mw = (COUT == 64) ? (wid & 3) : 0;
    const int nw = (COUT == 64) ? (wid >> 2) : wid;
    const int grp = lane >> 2, tig = lane & 3;
    const int bx = blockIdx.x;
    const int ph = bx & 1, tile = bx >> 1;
    const int n = blockIdx.y;
    const int r0 = tile * TR;
    const int rlo = ph ? 0 : -1;
    const int coW = mw * 16;
    const float* inb = in + (size_t)n * 64 * HIN * HIN;
    float acc[2][4][4];
    #pragma unroll
    for (int pw = 0; pw < 2; ++pw)
        #pragma unroll
        for (int nt = 0; nt < 4; ++nt)
            #pragma unroll
            for (int i = 0; i < 4; ++i) acc[pw][nt][i] = 0.f;

    for (int ci0 = 0; ci0 < 64; ci0 += 8) {
        __syncthreads();
        for (int i = t; i < 8 * CIS0; i += 256) {
            int ci = i / CIS0, r2 = i - ci * CIS0;
            int rr = r2 / CP, cc = r2 - rr * CP;
            int gr = r0 + rlo + rr, gc = cc - 1;
            float v = 0.f;
            if ((unsigned)gr < (unsigned)HIN && (unsigned)gc < (unsigned)HIN) {
                v = inb[(ci0 + ci) * (HIN * HIN) + gr * HIN + gc];
                if (PRERELU) v = fmaxf(v, 0.f);
            }
            sIn[ci * CIS + r2] = f2tf(v);
        }
        {
            const unsigned* wtc = wt + (ph * 8 + (ci0 >> 3)) * 4096;
            for (int i = t; i < 4096; i += 256)
                sW[(i >> 6) * 72 + (i & 63)] = wtc[i];
        }
        __syncthreads();
        #pragma unroll
        for (int t4 = 0; t4 < 4; ++t4) {
            const int dh = t4 >> 1, dw = t4 & 1;
            #pragma unroll
            for (int pw = 0; pw < 2; ++pw) {
                const unsigned* wrow = sW + ((pw * 4 + t4) * 8) * 72 + coW + grp;
                unsigned a0 = wrow[tig * 72];
                unsigned a1 = wrow[tig * 72 + 8];
                unsigned a2 = wrow[(tig + 4) * 72];
                unsigned a3 = wrow[(tig + 4) * 72 + 8];
                #pragma unroll
                for (int nt = 0; nt < 4; ++nt) {
                    int sidx = nw * 32 + nt * 8;
                    int row = sidx / CW, colb = sidx - row * CW;
                    int idx = (row + dh) * CP + colb + grp + dw + pw;
                    unsigned b0 = sIn[tig * CIS + idx];
                    unsigned b1 = sIn[(tig + 4) * CIS + idx];
                    mma_tf32(acc[pw][nt][0], acc[pw][nt][1],
                             acc[pw][nt][2], acc[pw][nt][3],
                             a0, a1, a2, a3, b0, b1);
                }
            }
        }
    }
    const int co1 = coW + grp, co2 = co1 + 8;
    const bool v2 = (co2 < COUT);
    float b1v = bias[co1];
    float b2v = v2 ? bias[co2] : 0.f;
    float* ob = out + (size_t)n * COUT * ((size_t)OUTW * OUTW);
    const float* xb = TANH_LOSS ? xref + (size_t)n * COUT * ((size_t)OUTW * OUTW) : nullptr;
    float ls = 0.f;
    #pragma unroll
    for (int nt = 0; nt < 4; ++nt) {
        int sidx = nw * 32 + nt * 8;
        int row = sidx / CW, colb = sidx - row * CW;
        int oh = 2 * (r0 + row) + ph;
        int c = colb + 2 * tig;
        size_t b1a = (size_t)co1 * (OUTW * OUTW) + (size_t)oh * OUTW + 2 * c;
        size_t b2a = (size_t)co2 * (OUTW * OUTW) + (size_t)oh * OUTW + 2 * c;
        #pragma unroll
        for (int j = 0; j < 2; ++j) {   // frag cols c, c+1 -> wo base 2c, 2c+2
            float2 o1; o1.x = acc[0][nt][j] + b1v; o1.y = acc[1][nt][j] + b1v;
            float2 o2; o2.x = acc[0][nt][2 + j] + b2v; o2.y = acc[1][nt][2 + j] + b2v;
            size_t a1i = b1a + 2 * j, a2i = b2a + 2 * j;
            if (TANH_LOSS) {
                o1.x = tanhf(o1.x); o1.y = tanhf(o1.y);
                float2 x1 = *(const float2*)&xb[a1i];
                float d0 = o1.x - x1.x, d1 = o1.y - x1.y;
                ls += d0 * d0 + d1 * d1;
                *(float2*)&ob[a1i] = o1;
                if (v2) {
                    o2.x = tanhf(o2.x); o2.y = tanhf(o2.y);
                    float2 x2 = *(const float2*)&xb[a2i];
                    float e0 = o2.x - x2.x, e1 = o2.y - x2.y;
                    ls += e0 * e0 + e1 * e1;
                    *(float2*)&ob[a2i] = o2;
                }
            } else {
                o1.x = fmaxf(o1.x, 0.f); o1.y = fmaxf(o1.y, 0.f);
                *(float2*)&ob[a1i] = o1;
                if (v2) {
                    o2.x = fmaxf(o2.x, 0.f); o2.y = fmaxf(o2.y, 0.f);
                    *(float2*)&ob[a2i] = o2;
                }
            }
        }
    }
    if (TANH_LOSS) {
        float s = block_sum(ls);
        if (t == 0) atomicAdd(&g_recon_ss, (double)s);
    }
}

// ---------------- VQ ----------------
__global__ void cnorm_k(const float* __restrict__ cb) {
    int k = blockIdx.x * 256 + threadIdx.x;
    if (k < 2048) {
        float s = 0.f;
        #pragma unroll
        for (int d = 0; d < 64; ++d) { float c = cb[k * 64 + d]; s += c * c; }
        g_cnorm[k] = s;
    }
}

__global__ __launch_bounds__(128) void vq_assign_k(
    const float* __restrict__ z, const float* __restrict__ cb)
{
    __shared__ __align__(16) float4 sc[128 * 16];
    __shared__ float  sn[128];
    const int row = blockIdx.x * 128 + threadIdx.x;
    const int q0 = blockIdx.y * 512;
    const int b = row >> 10, hw = row & 1023;
    u64 zr2[32];
    const float* zp = z + ((size_t)b * 64) * 1024 + hw;
    #pragma unroll
    for (int d2 = 0; d2 < 32; ++d2)
        zr2[d2] = pack2(zp[(2 * d2) * 1024], zp[(2 * d2 + 1) * 1024]);
    float best = 3.4e38f; int bi = 0;
    const float4* cb4 = (const float4*)cb;
    for (int k0 = q0; k0 < q0 + 512; k0 += 128) {
        __syncthreads();
        for (int i = threadIdx.x; i < 128 * 16; i += 128) sc[i] = cb4[k0 * 16 + i];
        sn[threadIdx.x] = g_cnorm[k0 + threadIdx.x];
        __syncthreads();
        for (int kk = 0; kk < 128; ++kk) {
            const ulonglong2* cp = (const ulonglong2*)(sc + kk * 16);
            u64 a0 = 0ull, a1 = 0ull, a2 = 0ull, a3 = 0ull;
            #pragma unroll
            for (int j = 0; j < 8; ++j) {
                ulonglong2 c0 = cp[2 * j], c1 = cp[2 * j + 1];
                ffma2(a0, zr2[4 * j + 0], c0.x);
                ffma2(a1, zr2[4 * j + 1], c0.y);
                ffma2(a2, zr2[4 * j + 2], c1.x);
                ffma2(a3, zr2[4 * j + 3], c1.y);
            }
            u64 s2 = fadd2(fadd2(a0, a1), fadd2(a2, a3));
            float2 f = unpk(s2);
            float dist = sn[kk] - 2.f * (f.x + f.y);
            if (dist < best) { best = dist; bi = k0 + kk; }
        }
    }
    unsigned int fb = __float_as_uint(best);
    unsigned int key = fb ^ (((int)fb >> 31) | 0x80000000u);
    u64 packed = ((u64)key << 32) | (unsigned)bi;
    atomicMin(&g_best[row], packed);
}

__global__ __launch_bounds__(256) void vq_gather_k(
    const float* __restrict__ z, const float* __restrict__ cb,
    float* __restrict__ quant)
{
    int gid = blockIdx.x * 256 + threadIdx.x;
    int b = gid >> 16;
    int rem = gid & 65535;
    int d = rem >> 10;
    int hw = rem & 1023;
    int k = (int)(unsigned)(g_best[(b << 10) + hw] & 0xFFFFFFFFull);
    float q = cb[k * 64 + d];
    float zv = z[gid];
    quant[gid] = q;
    float diff = q - zv;
    float s = block_sum(diff * diff);
    if (threadIdx.x == 0) atomicAdd(&g_vq_ss, (double)s);
}

__global__ void vq_counts_k() {
    int i = blockIdx.x * 256 + threadIdx.x;
    if (i < 32768) {
        int k = (int)(unsigned)(g_best[i] & 0xFFFFFFFFull);
        atomicAdd(&g_counts[k], 1.0f);
    }
}

// ---------------- finalize ----------------
__global__ void finalize_k(float* __restrict__ out2) {
    float s = 0.f;
    for (int k = threadIdx.x; k < 2048; k += 256) {
        float p = g_counts[k] * (1.0f / 32768.0f);
        s += p * logf(p + 1e-10f);
    }
    float tot = block_sum(s);
    if (threadIdx.x == 0) {
        float perp = expf(-tot);
        float loss = (float)(g_recon_ss / 31457280.0 + 1.25 * (g_vq_ss / 2097152.0));
        out2[0] = loss;
        out2[1] = perp;
    }
}

// ---------------- launcher ----------------
extern "C" void kernel_launch(void* const* d_in, const int* in_sizes, int n_in,
                              void* d_out, int out_size) {
    const float* x          = (const float*)d_in[0];
    const float* ew1        = (const float*)d_in[1];
    const float* eb1        = (const float*)d_in[2];
    const float* ew2        = (const float*)d_in[3];
    const float* eb2        = (const float*)d_in[4];
    const float* ew3        = (const float*)d_in[5];
    const float* eb3        = (const float*)d_in[6];
    const float* enc_bn     = (const float*)d_in[7];
    const float* enc_res_w3 = (const float*)d_in[8];
    const float* enc_res_b3 = (const float*)d_in[9];
    const float* enc_res_w1 = (const float*)d_in[10];
    const float* enc_res_b1 = (const float*)d_in[11];
    const float* enc_res_bn = (const float*)d_in[12];
    const float* enc_out_w  = (const float*)d_in[13];
    const float* enc_out_b  = (const float*)d_in[14];
    const float* codebook   = (const float*)d_in[15];
    const float* dec_in_w   = (const float*)d_in[16];
    const float* dec_in_b   = (const float*)d_in[17];
    const float* dec_res_w3 = (const float*)d_in[18];
    const float* dec_res_b3 = (const float*)d_in[19];
    const float* dec_res_w1 = (const float*)d_in[20];
    const float* dec_res_b1 = (const float*)d_in[21];
    const float* dec_res_bn = (const float*)d_in[22];
    const float* dt_w1      = (const float*)d_in[23];
    const float* dt_b1      = (const float*)d_in[24];
    const float* dt_w2      = (const float*)d_in[25];
    const float* dt_b2      = (const float*)d_in[26];
    const float* dt_w3      = (const float*)d_in[27];
    const float* dt_b3      = (const float*)d_in[28];

    void *pa, *pb, *pc, *pw;
    cudaGetSymbolAddress(&pa, g_bufA);
    cudaGetSymbolAddress(&pb, g_bufB);
    cudaGetSymbolAddress(&pc, g_bufC);
    cudaGetSymbolAddress(&pw, g_wt);
    float* A  = (float*)pa;
    float* Bb = (float*)pb;
    float* Cc = (float*)pc;
    const unsigned* W = (const unsigned*)pw;
    float* out = (float*)d_out;

    const int smem1 = (16 * 8 * 72 + 8 * 1032) * 4;   // OW=128
    const int smem2 = (16 * 8 * 72 + 8 * 808)  * 4;   // OW=64
    const int smem3 = (16 * 8 * 72 + 8 * 680)  * 4;   // OW=32
    cudaFuncSetAttribute(conv4s2_mma<15, 128, true >,
                         cudaFuncAttributeMaxDynamicSharedMemorySize, smem1);
    cudaFuncSetAttribute(conv4s2_mma<64, 64, true >,
                         cudaFuncAttributeMaxDynamicSharedMemorySize, smem2);
    cudaFuncSetAttribute(conv4s2_mma<64, 32, false>,
                         cudaFuncAttributeMaxDynamicSharedMemorySize, smem3);

    init_k<<<128, 256>>>();
    wprep4_k<<<576, 256>>>(ew1, ew2, ew3);
    wprep3_k<<<1296, 256>>>(enc_res_w3, dec_in_w, dec_res_w3);
    wprep1_k<<<144, 256>>>(enc_res_w1, dec_res_w1, enc_out_w);
    wprepT_k<<<768, 256>>>(dt_w1, dt_w2, dt_w3);

    // ---- Encoder ----
    conv4s2_mma<15, 128, true ><<<dim3(128, 32), 256, smem1>>>(x,  A,  W + WT4_1, eb1, enc_bn);
    conv4s2_mma<64, 64,  true ><<<dim3(32, 32),  256, smem2>>>(A,  Bb, W + WT4_2, eb2, enc_bn + 256);
    conv4s2_mma<64, 32,  false><<<dim3(8, 32),   256, smem3>>>(Bb, A,  W + WT4_3, eb3, enc_bn + 512);
    for (int i = 0; i < 4; ++i) {
        conv3x3_mma<true, true><<<dim3(8, 32), 256>>>(
            A, Bb, W + WT3 + i * 36864, enc_res_b3 + i * 64,
            enc_res_bn + i * 512);
        conv1x1_mma<true, true, true><<<dim3(8, 32), 256>>>(
            Bb, A, A, W + WT1 + i * 4096, enc_res_b1 + i * 64,
            enc_res_bn + i * 512 + 256);
    }
    conv1x1_mma<false, false, false><<<dim3(8, 32), 256>>>(
        A, nullptr, Bb, W + WT1 + 8 * 4096, enc_out_b, nullptr);   // z -> Bb

    // ---- VQ ----
    cnorm_k<<<8, 256>>>(codebook);
    vq_assign_k<<<dim3(256, 4), 128>>>(Bb, codebook);
    vq_gather_k<<<8192, 256>>>(Bb, codebook, A);            // quant -> A
    vq_counts_k<<<128, 256>>>();

    // ---- Decoder ----
    conv3x3_mma<false, false><<<dim3(8, 32), 256>>>(
        A, Bb, W + WT3 + 4 * 36864, dec_in_b, nullptr);
    for (int i = 0; i < 4; ++i) {
        conv3x3_mma<true, true><<<dim3(8, 32), 256>>>(
            Bb, Cc, W + WT3 + (5 + i) * 36864, dec_res_b3 + i * 64,
            dec_res_bn + i * 512);
        conv1x1_mma<true, true, true><<<dim3(8, 32), 256>>>(
            Cc, Bb, Bb, W + WT1 + (4 + i) * 4096, dec_res_b1 + i * 64,
            dec_res_bn + i * 512 + 256);
    }
    convt_mma<64, 64,  true,  false><<<dim3(32, 32),  256>>>(Bb, A,   W + WTT1, dt_b1, nullptr);
    convt_mma<64, 128, false, false><<<dim3(128, 32), 256>>>(A,  Bb,  W + WTT2, dt_b2, nullptr);
    convt_mma<15, 256, false, true ><<<dim3(128, 32), 256>>>(Bb, out, W + WTT3, dt_b3, x);

    finalize_k<<<1, 256>>>(out + (out_size - 2));
}